// round 1
// baseline (speedup 1.0000x reference)
#include <cuda_runtime.h>
#include <cuda_fp16.h>
#include <mma.h>

using namespace nvcuda;

#define HH 4
#define BB 4
#define NN 2048
#define FF 128
#define UU 64
#define LOG2E 1.4426950408889634f

#define JC 4
#define JCHUNK 512
#define NCTA2 (BB*16*JC)   // 256
#define PLD 136            // padded leading dim for P tile (fp16), multiple of 8

// ---------------- scratch (static device globals; no runtime allocation) ----
__device__ __half g_proj[HH*BB*NN*UU];        // 4 MB  fp16 projections
__device__ float  g_s[HH*BB*NN];              // attention scalars s
__device__ float  g_spos[HH*BB];
__device__ float  g_sneg[HH*BB];
__device__ float  g_Opart[8388608];           // [NCTA2][H][128][64] partial numerators (33.5 MB)
__device__ float  g_Zpart[NCTA2*HH*128];      // partial denominators

__device__ __forceinline__ float ex2f(float x) {
    float y; asm("ex2.approx.f32 %0, %1;" : "=f"(y) : "f"(x)); return y;
}

// ---------------- Kernel 1: proj = relu(x@W + b), s = proj.a_w + a_b --------
__global__ __launch_bounds__(256) void k_proj(const float* __restrict__ x,
                                              const float* __restrict__ W,
                                              const float* __restrict__ bias,
                                              const float* __restrict__ a_w,
                                              const float* __restrict__ a_b)
{
    __shared__ float Wsm[16][UU];      // 4 KB  f-chunk of W
    __shared__ float xsm[256][17];     // 17.4 KB (pad 17 -> conflict-free)
    __shared__ float bsm[UU], awsm[UU];

    int h = blockIdx.z, b = blockIdx.y;
    int n0 = blockIdx.x * 256;
    int tid = threadIdx.x;

    if (tid < UU) { bsm[tid] = bias[h*UU + tid]; awsm[tid] = a_w[h*UU + tid]; }

    float acc[UU];
    #pragma unroll
    for (int u = 0; u < UU; u++) acc[u] = 0.f;

    const float* xb = x + ((size_t)b*NN + n0)*FF;
    const float* Wb = W + (size_t)h*FF*UU;

    for (int fc = 0; fc < FF; fc += 16) {
        __syncthreads();
        for (int k = tid; k < 16*UU; k += 256)
            Wsm[k>>6][k&63] = Wb[(size_t)(fc + (k>>6))*UU + (k&63)];
        for (int k = tid; k < 256*16; k += 256) {
            int r = k >> 4, f = k & 15;
            xsm[r][f] = xb[(size_t)r*FF + fc + f];
        }
        __syncthreads();
        #pragma unroll
        for (int f = 0; f < 16; f++) {
            float xv = xsm[tid][f];
            #pragma unroll
            for (int u = 0; u < UU; u += 4) {
                float4 wv = *(const float4*)&Wsm[f][u];
                acc[u]   = fmaf(xv, wv.x, acc[u]);
                acc[u+1] = fmaf(xv, wv.y, acc[u+1]);
                acc[u+2] = fmaf(xv, wv.z, acc[u+2]);
                acc[u+3] = fmaf(xv, wv.w, acc[u+3]);
            }
        }
    }

    float s = 0.f;
    __half2* pout = (__half2*)(g_proj + ((size_t)(h*BB+b)*NN + n0 + tid)*UU);
    #pragma unroll
    for (int u = 0; u < UU; u += 2) {
        float p0 = fmaxf(acc[u]   + bsm[u],   0.f);
        float p1 = fmaxf(acc[u+1] + bsm[u+1], 0.f);
        s = fmaf(p0, awsm[u],   s);
        s = fmaf(p1, awsm[u+1], s);
        pout[u>>1] = __floats2half2_rn(p0, p1);
    }
    s += a_b[h];
    g_s[(size_t)(h*BB+b)*NN + n0 + tid] = s;
}

// ---------------- Kernel 1b: per-(h,b) max/min of s --------------------------
__global__ __launch_bounds__(256) void k_minmax()
{
    __shared__ float smx[256], smn[256];
    int hb = blockIdx.x, tid = threadIdx.x;
    float mx = -1e30f, mn = 1e30f;
    for (int k = tid; k < NN; k += 256) {
        float v = g_s[(size_t)hb*NN + k];
        mx = fmaxf(mx, v); mn = fminf(mn, v);
    }
    smx[tid] = mx; smn[tid] = mn;
    __syncthreads();
    for (int off = 128; off > 0; off >>= 1) {
        if (tid < off) {
            smx[tid] = fmaxf(smx[tid], smx[tid+off]);
            smn[tid] = fminf(smn[tid], smn[tid+off]);
        }
        __syncthreads();
    }
    if (tid == 0) { g_spos[hb] = smx[0]; g_sneg[hb] = smn[0]; }
}

// ---------------- Kernel 2: masked-exp P tiles + fp16 MMA aggregation -------
// grid: 256 CTAs = (b, i-tile of 128, j-chunk of 512); 256 threads (8 warps)
__global__ __launch_bounds__(256) void k_attn(const int* __restrict__ adj)
{
    extern __shared__ char smem[];
    float*    s_il2e = (float*)smem;                 // [4][128] s_i * log2e
    float*    s_mhat = s_il2e + 512;                 // [4][128] mhat * log2e
    float*    sjs    = s_mhat + 512;                 // [4][512] s_j for this chunk
    unsigned* maskb  = (unsigned*)(sjs + 2048);      // [128][16] adjacency bitmask
    __half*   Psm    = (__half*)(maskb + 2048);      // [128][PLD]
    __half*   projsm = Psm + 128*PLD;                // [128][64]

    int cidx = blockIdx.x;
    int b = cidx >> 6, it = (cidx >> 2) & 15, jc = cidx & 3;
    int tid = threadIdx.x, lane = tid & 31, wid = tid >> 5;

    // s_i scaled + per-row safe max bound
    for (int idx = tid; idx < 512; idx += 256) {
        int h = idx >> 7, r = idx & 127;
        float sv = g_s[(size_t)(h*BB+b)*NN + it*128 + r];
        float sp = g_spos[h*BB+b], sn = g_sneg[h*BB+b];
        float mh = (sv >= 0.f) ? sv*sp : sv*sn;   // >= max_j s_i*s_j
        s_il2e[idx] = sv * LOG2E;
        s_mhat[idx] = mh * LOG2E;
    }
    // s_j for all heads, this j-chunk
    for (int idx = tid; idx < 2048; idx += 256) {
        int h = idx >> 9, jl = idx & 511;
        sjs[idx] = g_s[(size_t)(h*BB+b)*NN + jc*JCHUNK + jl];
    }
    // adjacency -> bitmask (read adj exactly once; all 4 heads reuse)
    const int* adjb = adj + ((size_t)b*NN + it*128)*NN + jc*JCHUNK;
    for (int q = wid; q < 512; q += 8) {
        int ro = q >> 2, seg = q & 3;
        const int4 a4 = *(const int4*)(adjb + (size_t)ro*NN + seg*128 + lane*4);
        unsigned nib = (unsigned)(a4.x>0) | ((unsigned)(a4.y>0)<<1)
                     | ((unsigned)(a4.z>0)<<2) | ((unsigned)(a4.w>0)<<3);
        unsigned word = nib << ((lane & 7)*4);
        word |= __shfl_xor_sync(0xffffffffu, word, 1);
        word |= __shfl_xor_sync(0xffffffffu, word, 2);
        word |= __shfl_xor_sync(0xffffffffu, word, 4);
        if ((lane & 7) == 0) maskb[ro*16 + seg*4 + (lane>>3)] = word;
    }
    __syncthreads();

    int r = tid >> 1, ch = tid & 1;   // P-build: thread -> (row, col-half)
    for (int h = 0; h < HH; h++) {
        wmma::fragment<wmma::accumulator, 16,16,16, float> cacc[4];
        #pragma unroll
        for (int ut = 0; ut < 4; ut++) wmma::fill_fragment(cacc[ut], 0.f);
        float zacc = 0.f;
        float srl = s_il2e[h*128 + r];
        float mh  = s_mhat[h*128 + r];

        for (int jt = 0; jt < 4; jt++) {
            // load proj tile (B operand) for (h, jt)
            const int4* psrc = (const int4*)(g_proj +
                ((size_t)(h*BB+b)*NN + jc*JCHUNK + jt*128)*UU);
            int4* pdst = (int4*)projsm;
            for (int k = tid; k < 1024; k += 256) pdst[k] = psrc[k];

            // build P tile: exp2(srl*s_j - mh) where adj bit set, else 0
            #pragma unroll
            for (int w2 = 0; w2 < 2; w2++) {
                unsigned mw = maskb[r*16 + jt*4 + ch*2 + w2];
                int colbase = ch*64 + w2*32;
                const float* sjp = sjs + h*512 + jt*128 + colbase;
                #pragma unroll
                for (int k = 0; k < 16; k++) {
                    float2 sj2 = *(const float2*)(sjp + 2*k);
                    float e0 = 0.f, e1 = 0.f;
                    if (mw & (1u << (2*k))) e0 = ex2f(fmaf(srl, sj2.x, -mh));
                    if (mw & (2u << (2*k))) e1 = ex2f(fmaf(srl, sj2.y, -mh));
                    zacc += e0 + e1;
                    *(__half2*)&Psm[r*PLD + colbase + 2*k] = __floats2half2_rn(e0, e1);
                }
            }
            __syncthreads();

            // MMA: C[128,64] += P[128,128] @ proj[128,64]
            const __half* Ab = Psm + wid*16*PLD;
            #pragma unroll
            for (int ks = 0; ks < 8; ks++) {
                wmma::fragment<wmma::matrix_a, 16,16,16, __half, wmma::row_major> af;
                wmma::load_matrix_sync(af, Ab + ks*16, PLD);
                #pragma unroll
                for (int ut = 0; ut < 4; ut++) {
                    wmma::fragment<wmma::matrix_b, 16,16,16, __half, wmma::row_major> bf;
                    wmma::load_matrix_sync(bf, projsm + ks*16*UU + ut*16, UU);
                    wmma::mma_sync(cacc[ut], af, bf, cacc[ut]);
                }
            }
            __syncthreads();
        }

        // write partials
        float zt = zacc + __shfl_xor_sync(0xffffffffu, zacc, 1);
        if (ch == 0) g_Zpart[((size_t)cidx*HH + h)*128 + r] = zt;
        float* ob = g_Opart + (((size_t)cidx*HH + h)*128 + wid*16)*64;
        #pragma unroll
        for (int ut = 0; ut < 4; ut++)
            wmma::store_matrix_sync(ob + ut*16, cacc[ut], 64, wmma::mem_row_major);
    }
}

// ---------------- Kernel 3: combine j-chunks, divide by Z, mean heads -------
__global__ __launch_bounds__(256) void k_final(float* __restrict__ out)
{
    int it = blockIdx.x, b = blockIdx.y;
    int tid = threadIdx.x;
    int u = tid & 63, rg = tid >> 6;
    for (int rr = 0; rr < 32; rr++) {
        int r = rg*32 + rr;
        float acc = 0.f;
        #pragma unroll
        for (int h = 0; h < HH; h++) {
            float num = 0.f, zs = 0.f;
            #pragma unroll
            for (int jcc = 0; jcc < JC; jcc++) {
                int c = (b*16 + it)*4 + jcc;
                size_t base = ((size_t)c*HH + h)*128 + r;
                zs  += g_Zpart[base];
                num += g_Opart[base*64 + u];
            }
            acc += num / zs;
        }
        out[((size_t)b*NN + it*128 + r)*64 + u] = 0.25f * acc;
    }
}

// ---------------- launch ----------------------------------------------------
extern "C" void kernel_launch(void* const* d_in, const int* in_sizes, int n_in,
                              void* d_out, int out_size)
{
    const float* x   = (const float*)d_in[0];
    const int*   adj = (const int*)d_in[1];
    const float* W   = (const float*)d_in[2];
    const float* bia = (const float*)d_in[3];
    const float* aw  = (const float*)d_in[4];
    const float* ab  = (const float*)d_in[5];
    float* out = (float*)d_out;
    (void)in_sizes; (void)n_in; (void)out_size;

    cudaFuncSetAttribute(k_attn, cudaFuncAttributeMaxDynamicSharedMemorySize, 71680);

    dim3 g1(NN/256, BB, HH);
    k_proj<<<g1, 256>>>(x, W, bia, aw, ab);
    k_minmax<<<HH*BB, 256>>>();
    k_attn<<<NCTA2, 256, 71680>>>(adj);
    dim3 g3(16, BB);
    k_final<<<g3, 256>>>(out);
}

// round 3
// speedup vs baseline: 1.2449x; 1.2449x over previous
#include <cuda_runtime.h>
#include <cuda_fp16.h>
#include <mma.h>

using namespace nvcuda;

#define HH 4
#define BB 4
#define NN 2048
#define FF 128
#define UU 64
#define LOG2E 1.4426950408889634f

#define JC 4
#define JCHUNK 512
#define NCTA2 (BB*16*JC)   // 256
#define PLD 136            // P row stride in halves (272 B, mult of 16 B)

// ---------------- scratch ----------------------------------------------------
__device__ __half g_proj[HH*BB*NN*UU];        // 4 MB  fp16 projections
__device__ float  g_s[HH*BB*NN];
__device__ float  g_spos[HH*BB];
__device__ float  g_sneg[HH*BB];
__device__ float  g_Opart[8388608];           // [NCTA2][H][128][64]
__device__ float  g_Zpart[NCTA2*HH*128];

// masked exp2 pair: half2( m0 * 2^(srl*a+nmh), m1 * 2^(srl*b+nmh) )
__device__ __forceinline__ __half2 exm(float srl, float a, float b, float nmh, unsigned mk) {
    __half2 hh = __floats2half2_rn(fmaf(srl, a, nmh), fmaf(srl, b, nmh));
    unsigned u = *reinterpret_cast<unsigned*>(&hh);
    asm("ex2.approx.f16x2 %0, %0;" : "+r"(u));
    __half2 e = *reinterpret_cast<__half2*>(&u);
    __half2 m = *reinterpret_cast<__half2*>(&mk);
    return __hmul2(e, m);
}

// ---------------- Kernel 1: proj = relu(x@W + b), s = proj.a_w + a_b --------
__global__ __launch_bounds__(256) void k_proj(const float* __restrict__ x,
                                              const float* __restrict__ W,
                                              const float* __restrict__ bias,
                                              const float* __restrict__ a_w,
                                              const float* __restrict__ a_b)
{
    __shared__ float Wsm[16][UU];
    __shared__ float xsm[256][17];
    __shared__ float bsm[UU], awsm[UU];

    int h = blockIdx.z, b = blockIdx.y;
    int n0 = blockIdx.x * 256;
    int tid = threadIdx.x;

    if (tid < UU) { bsm[tid] = bias[h*UU + tid]; awsm[tid] = a_w[h*UU + tid]; }

    float acc[UU];
    #pragma unroll
    for (int u = 0; u < UU; u++) acc[u] = 0.f;

    const float* xb = x + ((size_t)b*NN + n0)*FF;
    const float* Wb = W + (size_t)h*FF*UU;

    for (int fc = 0; fc < FF; fc += 16) {
        __syncthreads();
        for (int k = tid; k < 16*UU; k += 256)
            Wsm[k>>6][k&63] = Wb[(size_t)(fc + (k>>6))*UU + (k&63)];
        for (int k = tid; k < 256*16; k += 256) {
            int r = k >> 4, f = k & 15;
            xsm[r][f] = xb[(size_t)r*FF + fc + f];
        }
        __syncthreads();
        #pragma unroll
        for (int f = 0; f < 16; f++) {
            float xv = xsm[tid][f];
            #pragma unroll
            for (int u = 0; u < UU; u += 4) {
                float4 wv = *(const float4*)&Wsm[f][u];
                acc[u]   = fmaf(xv, wv.x, acc[u]);
                acc[u+1] = fmaf(xv, wv.y, acc[u+1]);
                acc[u+2] = fmaf(xv, wv.z, acc[u+2]);
                acc[u+3] = fmaf(xv, wv.w, acc[u+3]);
            }
        }
    }

    float s = 0.f;
    __half2* pout = (__half2*)(g_proj + ((size_t)(h*BB+b)*NN + n0 + tid)*UU);
    #pragma unroll
    for (int u = 0; u < UU; u += 2) {
        float p0 = fmaxf(acc[u]   + bsm[u],   0.f);
        float p1 = fmaxf(acc[u+1] + bsm[u+1], 0.f);
        s = fmaf(p0, awsm[u],   s);
        s = fmaf(p1, awsm[u+1], s);
        pout[u>>1] = __floats2half2_rn(p0, p1);
    }
    s += a_b[h];
    g_s[(size_t)(h*BB+b)*NN + n0 + tid] = s;
}

// ---------------- Kernel 1b: per-(h,b) max/min of s --------------------------
__global__ __launch_bounds__(256) void k_minmax()
{
    __shared__ float smx[256], smn[256];
    int hb = blockIdx.x, tid = threadIdx.x;
    float mx = -1e30f, mn = 1e30f;
    for (int k = tid; k < NN; k += 256) {
        float v = g_s[(size_t)hb*NN + k];
        mx = fmaxf(mx, v); mn = fminf(mn, v);
    }
    smx[tid] = mx; smn[tid] = mn;
    __syncthreads();
    for (int off = 128; off > 0; off >>= 1) {
        if (tid < off) {
            smx[tid] = fmaxf(smx[tid], smx[tid+off]);
            smn[tid] = fminf(smn[tid], smn[tid+off]);
        }
        __syncthreads();
    }
    if (tid == 0) { g_spos[hb] = smx[0]; g_sneg[hb] = smn[0]; }
}

// ---------------- Kernel 2: per-warp P build + fp16 MMA, 1 barrier/iter -----
// smem layout (bytes), all fragment buffers 32B-aligned:
//   0      s_il2e[512]f        2048
//   2048   s_mhat[512]f        2048
//   4096   sjs[2048]f          8192
//   12288  maskb[16][128]u     8192
//   20480  zscr[8][320]f       10240
//   30720  lutm[4]u            16  (+16 pad)
//   30752  onesT[256]h         512
//   31264  Psm[128*PLD]h       34816
//   66080  projA[2][8192]h     32768
//   total  98848
#define SMEM_ATTN 98848

__global__ __launch_bounds__(256,2) void k_attn(const int* __restrict__ adj)
{
    extern __shared__ char smem[];
    float*    s_il2e = (float*)(smem);
    float*    s_mhat = (float*)(smem + 2048);
    float*    sjs    = (float*)(smem + 4096);
    unsigned* maskb  = (unsigned*)(smem + 12288);
    float*    zscr   = (float*)(smem + 20480);
    unsigned* lutm   = (unsigned*)(smem + 30720);
    __half*   onesT  = (__half*)(smem + 30752);
    __half*   Psm    = (__half*)(smem + 31264);
    __half*   projA  = (__half*)(smem + 66080);

    int cidx = blockIdx.x;
    int b = cidx >> 6, it = (cidx >> 2) & 15, jc = cidx & 3;
    int tid = threadIdx.x, lane = tid & 31, wid = tid >> 5;

    if (tid < 4)
        lutm[tid] = ((tid & 1) ? 0x00003C00u : 0u) | ((tid & 2) ? 0x3C000000u : 0u);
    onesT[tid] = ((tid & 15) == 0) ? __float2half(1.f) : __float2half(0.f);

    // s_i scaled + safe row max bound (global over j)
    for (int idx = tid; idx < 512; idx += 256) {
        int h = idx >> 7, r = idx & 127;
        float sv = g_s[(size_t)(h*BB+b)*NN + it*128 + r];
        float sp = g_spos[h*BB+b], sn = g_sneg[h*BB+b];
        float mh = (sv >= 0.f) ? sv*sp : sv*sn;
        s_il2e[idx] = sv * LOG2E;
        s_mhat[idx] = mh * LOG2E;
    }
    for (int idx = tid; idx < 2048; idx += 256) {
        int h = idx >> 9, jl = idx & 511;
        sjs[idx] = g_s[(size_t)(h*BB+b)*NN + jc*JCHUNK + jl];
    }
    // adjacency -> bitmask, transposed [word][row] (read once; all heads reuse)
    const int* adjb = adj + ((size_t)b*NN + it*128)*NN + jc*JCHUNK;
    for (int q = wid; q < 512; q += 8) {
        int ro = q >> 2, seg = q & 3;
        const int4 a4 = *(const int4*)(adjb + (size_t)ro*NN + seg*128 + lane*4);
        unsigned nib = (unsigned)(a4.x>0) | ((unsigned)(a4.y>0)<<1)
                     | ((unsigned)(a4.z>0)<<2) | ((unsigned)(a4.w>0)<<3);
        unsigned word = nib << ((lane & 7)*4);
        word |= __shfl_xor_sync(0xffffffffu, word, 1);
        word |= __shfl_xor_sync(0xffffffffu, word, 2);
        word |= __shfl_xor_sync(0xffffffffu, word, 4);
        if ((lane & 7) == 0) maskb[(seg*4 + (lane>>3))*128 + ro] = word;
    }
    // prologue: proj tile for iter 0 -> buffer 0
    {
        const int4* psrc = (const int4*)(g_proj + ((size_t)b*NN + jc*JCHUNK)*UU);
        int4* pdst = (int4*)projA;
        for (int k = tid; k < 1024; k += 256) pdst[k] = psrc[k];
    }
    __syncthreads();

    wmma::fragment<wmma::matrix_b,16,16,16,__half,wmma::row_major> bones;
    wmma::load_matrix_sync(bones, onesT, 16);

    int rl = lane & 15, ch = lane >> 4;        // conflict-free store mapping
    int r = wid*16 + rl;
    __half* prow = Psm + r*PLD + ch*64;

    wmma::fragment<wmma::accumulator,16,16,16,float> cacc[5];

    for (int iter = 0; iter < 16; iter++) {
        int h = iter >> 2, jt = iter & 3;
        const __half* bufc = projA + (iter & 1)*8192;

        if (iter) __syncthreads();   // prior-iter MMA reads of next buffer done

        if (iter + 1 < 16) {         // prefetch next proj tile
            int hn = (iter+1) >> 2, jtn = (iter+1) & 3;
            const int4* psrc = (const int4*)(g_proj +
                ((size_t)(hn*BB+b)*NN + jc*JCHUNK + jtn*128)*UU);
            int4* pdst = (int4*)(projA + ((iter+1)&1)*8192);
            for (int k = tid; k < 1024; k += 256) pdst[k] = psrc[k];
        }

        if (jt == 0) {
            #pragma unroll
            for (int t = 0; t < 5; t++) wmma::fill_fragment(cacc[t], 0.f);
        }

        // ---- build this warp's 16 P rows (lane: row rl, cols ch*64..+63)
        {
            float srl = s_il2e[h*128 + r];
            float nmh = -s_mhat[h*128 + r];
            const float4* sjp = (const float4*)(sjs + h*512 + jt*128 + ch*64);
            unsigned mw0 = maskb[(jt*4 + ch*2    )*128 + r];
            unsigned mw1 = maskb[(jt*4 + ch*2 + 1)*128 + r];
            #pragma unroll
            for (int g = 0; g < 8; g++) {
                float4 A = sjp[2*g], B = sjp[2*g+1];
                unsigned mb = ((g < 4) ? mw0 : mw1) >> ((g & 3)*8);
                __half2 e0 = exm(srl, A.x, A.y, nmh, lutm[mb & 3]);
                __half2 e1 = exm(srl, A.z, A.w, nmh, lutm[(mb>>2) & 3]);
                __half2 e2 = exm(srl, B.x, B.y, nmh, lutm[(mb>>4) & 3]);
                __half2 e3 = exm(srl, B.z, B.w, nmh, lutm[(mb>>6) & 3]);
                uint4 st;
                st.x = *reinterpret_cast<unsigned*>(&e0);
                st.y = *reinterpret_cast<unsigned*>(&e1);
                st.z = *reinterpret_cast<unsigned*>(&e2);
                st.w = *reinterpret_cast<unsigned*>(&e3);
                ((uint4*)prow)[g] = st;
            }
        }
        __syncwarp();

        // ---- MMA: C[16,64] += P_rows[16,128] @ proj[128,64]; Z via ones col
        const __half* Ab = Psm + wid*16*PLD;
        #pragma unroll
        for (int ks = 0; ks < 8; ks++) {
            wmma::fragment<wmma::matrix_a,16,16,16,__half,wmma::row_major> af;
            wmma::load_matrix_sync(af, Ab + ks*16, PLD);
            #pragma unroll
            for (int ut = 0; ut < 4; ut++) {
                wmma::fragment<wmma::matrix_b,16,16,16,__half,wmma::row_major> bf;
                wmma::load_matrix_sync(bf, bufc + ks*16*UU + ut*16, UU);
                wmma::mma_sync(cacc[ut], af, bf, cacc[ut]);
            }
            wmma::mma_sync(cacc[4], af, bones, cacc[4]);
        }

        if (jt == 3) {
            float* ob = g_Opart + (((size_t)cidx*HH + h)*128 + wid*16)*64;
            #pragma unroll
            for (int ut = 0; ut < 4; ut++)
                wmma::store_matrix_sync(ob + ut*16, cacc[ut], 64, wmma::mem_row_major);
            float* zs = zscr + wid*320;
            wmma::store_matrix_sync(zs, cacc[4], 20, wmma::mem_row_major);
            __syncwarp();
            if (lane < 16)
                g_Zpart[((size_t)cidx*HH + h)*128 + wid*16 + lane] = zs[lane*20];
        }
    }
}

// ---------------- Kernel 3: combine, divide, head-mean (1 thread / element) -
__global__ __launch_bounds__(256) void k_final(float* __restrict__ out)
{
    int idx = blockIdx.x*256 + threadIdx.x;      // 0 .. 524287
    int u = idx & 63;
    int n = (idx >> 6) & 2047;
    int b = idx >> 17;
    int it = n >> 7, r = n & 127;

    float acc = 0.f;
    #pragma unroll
    for (int h = 0; h < HH; h++) {
        float z = 0.f, num = 0.f;
        #pragma unroll
        for (int jcc = 0; jcc < JC; jcc++) {
            int c = (b*16 + it)*4 + jcc;
            size_t base = ((size_t)c*HH + h)*128 + r;
            z   += g_Zpart[base];
            num += g_Opart[base*64 + u];
        }
        acc += num / z;
    }
    out[idx] = 0.25f * acc;
}

// ---------------- launch ----------------------------------------------------
extern "C" void kernel_launch(void* const* d_in, const int* in_sizes, int n_in,
                              void* d_out, int out_size)
{
    const float* x   = (const float*)d_in[0];
    const int*   adj = (const int*)d_in[1];
    const float* W   = (const float*)d_in[2];
    const float* bia = (const float*)d_in[3];
    const float* aw  = (const float*)d_in[4];
    const float* ab  = (const float*)d_in[5];
    float* out = (float*)d_out;
    (void)in_sizes; (void)n_in; (void)out_size;

    cudaFuncSetAttribute(k_attn, cudaFuncAttributeMaxDynamicSharedMemorySize, SMEM_ATTN);

    dim3 g1(NN/256, BB, HH);
    k_proj<<<g1, 256>>>(x, W, bia, aw, ab);
    k_minmax<<<HH*BB, 256>>>();
    k_attn<<<NCTA2, 256, SMEM_ATTN>>>(adj);
    k_final<<<(BB*NN*UU)/256, 256>>>(out);
}

// round 5
// speedup vs baseline: 2.2430x; 1.8017x over previous
#include <cuda_runtime.h>
#include <cuda_fp16.h>
#include <mma.h>

using namespace nvcuda;

#define HH 4
#define BB 4
#define NN 2048
#define FF 128
#define UU 64
#define LOG2E 1.4426950408889634f

#define JC 4
#define JCHUNK 512
#define NCTA2 (BB*16*JC)   // 256
#define PLD 136            // P row stride in halves (272 B): LDSM bank-advance 4/row
#define BLD 72             // proj B tile row stride in halves (144 B): conflict-free LDSM

// ---------------- scratch ----------------------------------------------------
__device__ __half g_proj[HH*BB*NN*UU];        // 4 MB  fp16 projections
__device__ float  g_s[HH*BB*NN];
__device__ float  g_spos[HH*BB];
__device__ float  g_sneg[HH*BB];
__device__ float  g_Opart[8388608];           // [NCTA2][H][128][64]
__device__ float  g_Zpart[NCTA2*HH*128];

// masked exp2 pair: half2( m0 * 2^(srl*a+nmh), m1 * 2^(srl*b+nmh) )
__device__ __forceinline__ __half2 exm(float srl, float a, float b, float nmh, unsigned mk) {
    __half2 hh = __floats2half2_rn(fmaf(srl, a, nmh), fmaf(srl, b, nmh));
    unsigned u = *reinterpret_cast<unsigned*>(&hh);
    asm("ex2.approx.f16x2 %0, %0;" : "+r"(u));
    __half2 e = *reinterpret_cast<__half2*>(&u);
    __half2 m = *reinterpret_cast<__half2*>(&mk);
    return __hmul2(e, m);
}

// ---------------- Kernel 1: proj = relu(x@W + b), s = proj.a_w + a_b --------
__global__ __launch_bounds__(256) void k_proj(const float* __restrict__ x,
                                              const float* __restrict__ W,
                                              const float* __restrict__ bias,
                                              const float* __restrict__ a_w,
                                              const float* __restrict__ a_b)
{
    __shared__ float Wsm[16][UU];
    __shared__ float xsm[256][17];
    __shared__ float bsm[UU], awsm[UU];

    int h = blockIdx.z, b = blockIdx.y;
    int n0 = blockIdx.x * 256;
    int tid = threadIdx.x;

    if (tid < UU) { bsm[tid] = bias[h*UU + tid]; awsm[tid] = a_w[h*UU + tid]; }

    float acc[UU];
    #pragma unroll
    for (int u = 0; u < UU; u++) acc[u] = 0.f;

    const float* xb = x + ((size_t)b*NN + n0)*FF;
    const float* Wb = W + (size_t)h*FF*UU;

    for (int fc = 0; fc < FF; fc += 16) {
        __syncthreads();
        for (int k = tid; k < 16*UU; k += 256)
            Wsm[k>>6][k&63] = Wb[(size_t)(fc + (k>>6))*UU + (k&63)];
        for (int k = tid; k < 256*16; k += 256) {
            int r = k >> 4, f = k & 15;
            xsm[r][f] = xb[(size_t)r*FF + fc + f];
        }
        __syncthreads();
        #pragma unroll
        for (int f = 0; f < 16; f++) {
            float xv = xsm[tid][f];
            #pragma unroll
            for (int u = 0; u < UU; u += 4) {
                float4 wv = *(const float4*)&Wsm[f][u];
                acc[u]   = fmaf(xv, wv.x, acc[u]);
                acc[u+1] = fmaf(xv, wv.y, acc[u+1]);
                acc[u+2] = fmaf(xv, wv.z, acc[u+2]);
                acc[u+3] = fmaf(xv, wv.w, acc[u+3]);
            }
        }
    }

    float s = 0.f;
    __half2* pout = (__half2*)(g_proj + ((size_t)(h*BB+b)*NN + n0 + tid)*UU);
    #pragma unroll
    for (int u = 0; u < UU; u += 2) {
        float p0 = fmaxf(acc[u]   + bsm[u],   0.f);
        float p1 = fmaxf(acc[u+1] + bsm[u+1], 0.f);
        s = fmaf(p0, awsm[u],   s);
        s = fmaf(p1, awsm[u+1], s);
        pout[u>>1] = __floats2half2_rn(p0, p1);
    }
    s += a_b[h];
    g_s[(size_t)(h*BB+b)*NN + n0 + tid] = s;
}

// ---------------- Kernel 1b: per-(h,b) max/min of s --------------------------
__global__ __launch_bounds__(256) void k_minmax()
{
    __shared__ float smx[256], smn[256];
    int hb = blockIdx.x, tid = threadIdx.x;
    float mx = -1e30f, mn = 1e30f;
    for (int k = tid; k < NN; k += 256) {
        float v = g_s[(size_t)hb*NN + k];
        mx = fmaxf(mx, v); mn = fminf(mn, v);
    }
    smx[tid] = mx; smn[tid] = mn;
    __syncthreads();
    for (int off = 128; off > 0; off >>= 1) {
        if (tid < off) {
            smx[tid] = fmaxf(smx[tid], smx[tid+off]);
            smn[tid] = fminf(smn[tid], smn[tid+off]);
        }
        __syncthreads();
    }
    if (tid == 0) { g_spos[hb] = smx[0]; g_sneg[hb] = smn[0]; }
}

// ---------------- Kernel 2: per-warp P build + fp16 MMA, 1 barrier/iter -----
// smem layout (bytes), all fragment buffers 32B-aligned:
//   0      s_il2e[512]f        2048
//   2048   s_mhat[512]f        2048
//   4096   sjs[2048]f          8192
//   12288  maskb[16][128]u     8192
//   20480  zscr[8][320]f       10240
//   30720  lutm[4]u            16  (+16 pad)
//   30752  onesT[256]h         512
//   31264  Psm[128*PLD]h       34816
//   66080  projA[2][128*BLD]h  36864
//   total  102944
#define SMEM_ATTN 102944

__global__ __launch_bounds__(256,2) void k_attn(const int* __restrict__ adj)
{
    extern __shared__ char smem[];
    float*    s_il2e = (float*)(smem);
    float*    s_mhat = (float*)(smem + 2048);
    float*    sjs    = (float*)(smem + 4096);
    unsigned* maskb  = (unsigned*)(smem + 12288);
    float*    zscr   = (float*)(smem + 20480);
    unsigned* lutm   = (unsigned*)(smem + 30720);
    __half*   onesT  = (__half*)(smem + 30752);
    __half*   Psm    = (__half*)(smem + 31264);
    __half*   projA  = (__half*)(smem + 66080);

    int cidx = blockIdx.x;
    int b = cidx >> 6, it = (cidx >> 2) & 15, jc = cidx & 3;
    int tid = threadIdx.x, lane = tid & 31, wid = tid >> 5;

    if (tid < 4)
        lutm[tid] = ((tid & 1) ? 0x00003C00u : 0u) | ((tid & 2) ? 0x3C000000u : 0u);
    onesT[tid] = ((tid & 15) == 0) ? __float2half(1.f) : __float2half(0.f);

    // s_i scaled + safe row max bound (global over j)
    for (int idx = tid; idx < 512; idx += 256) {
        int h = idx >> 7, r = idx & 127;
        float sv = g_s[(size_t)(h*BB+b)*NN + it*128 + r];
        float sp = g_spos[h*BB+b], sn = g_sneg[h*BB+b];
        float mh = (sv >= 0.f) ? sv*sp : sv*sn;
        s_il2e[idx] = sv * LOG2E;
        s_mhat[idx] = mh * LOG2E;
    }
    for (int idx = tid; idx < 2048; idx += 256) {
        int h = idx >> 9, jl = idx & 511;
        sjs[idx] = g_s[(size_t)(h*BB+b)*NN + jc*JCHUNK + jl];
    }
    // adjacency -> bitmask, transposed [word][row] (read once; all heads reuse)
    const int* adjb = adj + ((size_t)b*NN + it*128)*NN + jc*JCHUNK;
    for (int q = wid; q < 512; q += 8) {
        int ro = q >> 2, seg = q & 3;
        const int4 a4 = *(const int4*)(adjb + (size_t)ro*NN + seg*128 + lane*4);
        unsigned nib = (unsigned)(a4.x>0) | ((unsigned)(a4.y>0)<<1)
                     | ((unsigned)(a4.z>0)<<2) | ((unsigned)(a4.w>0)<<3);
        unsigned word = nib << ((lane & 7)*4);
        word |= __shfl_xor_sync(0xffffffffu, word, 1);
        word |= __shfl_xor_sync(0xffffffffu, word, 2);
        word |= __shfl_xor_sync(0xffffffffu, word, 4);
        if ((lane & 7) == 0) maskb[(seg*4 + (lane>>3))*128 + ro] = word;
    }
    // prologue: proj tile for iter 0 -> buffer 0 (padded rows: BLD halves)
    {
        const int4* psrc = (const int4*)(g_proj + ((size_t)b*NN + jc*JCHUNK)*UU);
        for (int k = tid; k < 1024; k += 256) {
            int ro = k >> 3, cg = k & 7;
            *(int4*)(projA + ro*BLD + cg*8) = psrc[k];
        }
    }
    __syncthreads();

    wmma::fragment<wmma::matrix_b,16,16,16,__half,wmma::row_major> bones;
    wmma::load_matrix_sync(bones, onesT, 16);

    int rl = lane & 15, ch = lane >> 4;        // conflict-free store mapping
    int r = wid*16 + rl;
    __half* prow = Psm + r*PLD + ch*64;

    wmma::fragment<wmma::accumulator,16,16,16,float> cacc[5];

    for (int iter = 0; iter < 16; iter++) {
        int h = iter >> 2, jt = iter & 3;
        const __half* bufc = projA + (iter & 1)*(128*BLD);

        if (iter) __syncthreads();   // prior-iter MMA reads of next buffer done

        if (iter + 1 < 16) {         // prefetch next proj tile (padded)
            int hn = (iter+1) >> 2, jtn = (iter+1) & 3;
            const int4* psrc = (const int4*)(g_proj +
                ((size_t)(hn*BB+b)*NN + jc*JCHUNK + jtn*128)*UU);
            __half* pdst = projA + ((iter+1)&1)*(128*BLD);
            for (int k = tid; k < 1024; k += 256) {
                int ro = k >> 3, cg = k & 7;
                *(int4*)(pdst + ro*BLD + cg*8) = psrc[k];
            }
        }

        if (jt == 0) {
            #pragma unroll
            for (int t = 0; t < 5; t++) wmma::fill_fragment(cacc[t], 0.f);
        }

        // ---- build this warp's 16 P rows (lane: row rl, cols ch*64..+63)
        {
            float srl = s_il2e[h*128 + r];
            float nmh = -s_mhat[h*128 + r];
            const float4* sjp = (const float4*)(sjs + h*512 + jt*128 + ch*64);
            unsigned mw0 = maskb[(jt*4 + ch*2    )*128 + r];
            unsigned mw1 = maskb[(jt*4 + ch*2 + 1)*128 + r];
            #pragma unroll
            for (int g = 0; g < 8; g++) {
                float4 A = sjp[2*g], B = sjp[2*g+1];
                unsigned mb = ((g < 4) ? mw0 : mw1) >> ((g & 3)*8);
                __half2 e0 = exm(srl, A.x, A.y, nmh, lutm[mb & 3]);
                __half2 e1 = exm(srl, A.z, A.w, nmh, lutm[(mb>>2) & 3]);
                __half2 e2 = exm(srl, B.x, B.y, nmh, lutm[(mb>>4) & 3]);
                __half2 e3 = exm(srl, B.z, B.w, nmh, lutm[(mb>>6) & 3]);
                uint4 st;
                st.x = *reinterpret_cast<unsigned*>(&e0);
                st.y = *reinterpret_cast<unsigned*>(&e1);
                st.z = *reinterpret_cast<unsigned*>(&e2);
                st.w = *reinterpret_cast<unsigned*>(&e3);
                ((uint4*)prow)[g] = st;
            }
        }
        __syncwarp();

        // ---- MMA: C[16,64] += P_rows[16,128] @ proj[128,64]; Z via ones col
        const __half* Ab = Psm + wid*16*PLD;
        #pragma unroll
        for (int ks = 0; ks < 8; ks++) {
            wmma::fragment<wmma::matrix_a,16,16,16,__half,wmma::row_major> af;
            wmma::load_matrix_sync(af, Ab + ks*16, PLD);
            #pragma unroll
            for (int ut = 0; ut < 4; ut++) {
                wmma::fragment<wmma::matrix_b,16,16,16,__half,wmma::row_major> bf;
                wmma::load_matrix_sync(bf, bufc + ks*16*BLD + ut*16, BLD);
                wmma::mma_sync(cacc[ut], af, bf, cacc[ut]);
            }
            wmma::mma_sync(cacc[4], af, bones, cacc[4]);
        }

        if (jt == 3) {
            float* ob = g_Opart + (((size_t)cidx*HH + h)*128 + wid*16)*64;
            #pragma unroll
            for (int ut = 0; ut < 4; ut++)
                wmma::store_matrix_sync(ob + ut*16, cacc[ut], 64, wmma::mem_row_major);
            float* zs = zscr + wid*320;
            wmma::store_matrix_sync(zs, cacc[4], 20, wmma::mem_row_major);
            __syncwarp();
            if (lane < 16)
                g_Zpart[((size_t)cidx*HH + h)*128 + wid*16 + lane] = zs[lane*20];
        }
    }
}

// ---------------- Kernel 3: combine, divide, head-mean (1 thread / element) -
__global__ __launch_bounds__(256) void k_final(float* __restrict__ out)
{
    int idx = blockIdx.x*256 + threadIdx.x;      // 0 .. 524287
    int u = idx & 63;
    int n = (idx >> 6) & 2047;
    int b = idx >> 17;
    int it = n >> 7, r = n & 127;

    float acc = 0.f;
    #pragma unroll
    for (int h = 0; h < HH; h++) {
        float z = 0.f, num = 0.f;
        #pragma unroll
        for (int jcc = 0; jcc < JC; jcc++) {
            int c = (b*16 + it)*4 + jcc;
            size_t base = ((size_t)c*HH + h)*128 + r;
            z   += g_Zpart[base];
            num += g_Opart[base*64 + u];
        }
        acc += num / z;
    }
    out[idx] = 0.25f * acc;
}

// ---------------- launch ----------------------------------------------------
extern "C" void kernel_launch(void* const* d_in, const int* in_sizes, int n_in,
                              void* d_out, int out_size)
{
    const float* x   = (const float*)d_in[0];
    const int*   adj = (const int*)d_in[1];
    const float* W   = (const float*)d_in[2];
    const float* bia = (const float*)d_in[3];
    const float* aw  = (const float*)d_in[4];
    const float* ab  = (const float*)d_in[5];
    float* out = (float*)d_out;
    (void)in_sizes; (void)n_in; (void)out_size;

    cudaFuncSetAttribute(k_attn, cudaFuncAttributeMaxDynamicSharedMemorySize, SMEM_ATTN);

    dim3 g1(NN/256, BB, HH);
    k_proj<<<g1, 256>>>(x, W, bia, aw, ab);
    k_minmax<<<HH*BB, 256>>>();
    k_attn<<<NCTA2, 256, SMEM_ATTN>>>(adj);
    k_final<<<(BB*NN*UU)/256, 256>>>(out);
}

// round 6
// speedup vs baseline: 2.3908x; 1.0659x over previous
#include <cuda_runtime.h>
#include <cuda_fp16.h>
#include <cstdint>

#define HH 4
#define BB 4
#define NN 2048
#define FF 128
#define UU 64
#define LOG2E 1.4426950408889634f

#define JC 4
#define JCHUNK 512
#define NCTA2 (BB*16*JC)   // 256
#define BLD 72             // proj B tile row stride in halves (144 B): conflict-free

// ---------------- scratch ----------------------------------------------------
__device__ __half g_proj[HH*BB*NN*UU];        // 4 MB  fp16 projections
__device__ float  g_s[HH*BB*NN];
__device__ float  g_spos[HH*BB];
__device__ float  g_sneg[HH*BB];
__device__ float  g_Opart[8388608];           // [NCTA2][H][128][64]
__device__ float  g_Zpart[NCTA2*HH*128];

__device__ __forceinline__ uint32_t smem_u32(const void* p) {
    uint32_t a;
    asm("{ .reg .u64 t; cvta.to.shared.u64 t, %1; cvt.u32.u64 %0, t; }" : "=r"(a) : "l"(p));
    return a;
}

// pack two fp32 args to half2 and take ex2 of both
__device__ __forceinline__ uint32_t ex2pack(float x, float y) {
    __half2 hh = __floats2half2_rn(x, y);
    uint32_t u = *reinterpret_cast<uint32_t*>(&hh);
    asm("ex2.approx.f16x2 %0, %0;" : "+r"(u));
    return u;
}

#define MMA_F16(d, a0,a1,a2,a3, b0,b1) \
    asm volatile("mma.sync.aligned.m16n8k16.row.col.f32.f16.f16.f32 " \
        "{%0,%1,%2,%3}, {%4,%5,%6,%7}, {%8,%9}, {%0,%1,%2,%3};" \
        : "+f"((d)[0]), "+f"((d)[1]), "+f"((d)[2]), "+f"((d)[3]) \
        : "r"(a0), "r"(a1), "r"(a2), "r"(a3), "r"(b0), "r"(b1))

#define LDSM_X4_TRANS(r0,r1,r2,r3, addr) \
    asm volatile("ldmatrix.sync.aligned.m8n8.x4.trans.shared.b16 {%0,%1,%2,%3}, [%4];" \
        : "=r"(r0), "=r"(r1), "=r"(r2), "=r"(r3) : "r"(addr))

// ---------------- Kernel 1: proj = relu(x@W + b), s = proj.a_w + a_b --------
__global__ __launch_bounds__(256) void k_proj(const float* __restrict__ x,
                                              const float* __restrict__ W,
                                              const float* __restrict__ bias,
                                              const float* __restrict__ a_w,
                                              const float* __restrict__ a_b)
{
    __shared__ float Wsm[16][UU];
    __shared__ float xsm[256][17];
    __shared__ float bsm[UU], awsm[UU];

    int h = blockIdx.z, b = blockIdx.y;
    int n0 = blockIdx.x * 256;
    int tid = threadIdx.x;

    if (tid < UU) { bsm[tid] = bias[h*UU + tid]; awsm[tid] = a_w[h*UU + tid]; }

    float acc[UU];
    #pragma unroll
    for (int u = 0; u < UU; u++) acc[u] = 0.f;

    const float* xb = x + ((size_t)b*NN + n0)*FF;
    const float* Wb = W + (size_t)h*FF*UU;

    for (int fc = 0; fc < FF; fc += 16) {
        __syncthreads();
        for (int k = tid; k < 16*UU; k += 256)
            Wsm[k>>6][k&63] = Wb[(size_t)(fc + (k>>6))*UU + (k&63)];
        for (int k = tid; k < 256*16; k += 256) {
            int r = k >> 4, f = k & 15;
            xsm[r][f] = xb[(size_t)r*FF + fc + f];
        }
        __syncthreads();
        #pragma unroll
        for (int f = 0; f < 16; f++) {
            float xv = xsm[tid][f];
            #pragma unroll
            for (int u = 0; u < UU; u += 4) {
                float4 wv = *(const float4*)&Wsm[f][u];
                acc[u]   = fmaf(xv, wv.x, acc[u]);
                acc[u+1] = fmaf(xv, wv.y, acc[u+1]);
                acc[u+2] = fmaf(xv, wv.z, acc[u+2]);
                acc[u+3] = fmaf(xv, wv.w, acc[u+3]);
            }
        }
    }

    float s = 0.f;
    __half2* pout = (__half2*)(g_proj + ((size_t)(h*BB+b)*NN + n0 + tid)*UU);
    #pragma unroll
    for (int u = 0; u < UU; u += 2) {
        float p0 = fmaxf(acc[u]   + bsm[u],   0.f);
        float p1 = fmaxf(acc[u+1] + bsm[u+1], 0.f);
        s = fmaf(p0, awsm[u],   s);
        s = fmaf(p1, awsm[u+1], s);
        pout[u>>1] = __floats2half2_rn(p0, p1);
    }
    s += a_b[h];
    g_s[(size_t)(h*BB+b)*NN + n0 + tid] = s;
}

// ---------------- Kernel 1b: per-(h,b) max/min of s --------------------------
__global__ __launch_bounds__(256) void k_minmax()
{
    __shared__ float smx[256], smn[256];
    int hb = blockIdx.x, tid = threadIdx.x;
    float mx = -1e30f, mn = 1e30f;
    for (int k = tid; k < NN; k += 256) {
        float v = g_s[(size_t)hb*NN + k];
        mx = fmaxf(mx, v); mn = fminf(mn, v);
    }
    smx[tid] = mx; smn[tid] = mn;
    __syncthreads();
    for (int off = 128; off > 0; off >>= 1) {
        if (tid < off) {
            smx[tid] = fmaxf(smx[tid], smx[tid+off]);
            smn[tid] = fminf(smn[tid], smn[tid+off]);
        }
        __syncthreads();
    }
    if (tid == 0) { g_spos[hb] = smx[0]; g_sneg[hb] = smn[0]; }
}

// ---------------- Kernel 2: register-A mma.m16n8k16 attention ---------------
// smem layout (bytes):
//   0      s_il2e[512]f        2048
//   2048   s_mhat[512]f        2048
//   4096   sjs[2048]f          8192
//   12288  maskb[16][128]u     8192
//   20480  projB[2][128*BLD]h  36864
//   total  57344  -> 3 CTAs/SM
#define SMEM_ATTN 57344
#define ONEH2 0x3C003C00u
#define NEGBIG (-100.0f)

__global__ __launch_bounds__(256,3) void k_attn(const int* __restrict__ adj)
{
    extern __shared__ char smem[];
    float*    s_il2e = (float*)(smem);
    float*    s_mhat = (float*)(smem + 2048);
    float*    sjs    = (float*)(smem + 4096);
    unsigned* maskb  = (unsigned*)(smem + 12288);
    __half*   projB  = (__half*)(smem + 20480);
    uint32_t  projB_u32 = smem_u32(projB);

    int cidx = blockIdx.x;
    int b = cidx >> 6, it = (cidx >> 2) & 15, jc = cidx & 3;
    int tid = threadIdx.x, lane = tid & 31, wid = tid >> 5;
    int g = lane >> 2, tg2 = (lane & 3)*2;

    // s_i scaled + safe row max bound (global over j)
    for (int idx = tid; idx < 512; idx += 256) {
        int h = idx >> 7, r = idx & 127;
        float sv = g_s[(size_t)(h*BB+b)*NN + it*128 + r];
        float sp = g_spos[h*BB+b], sn = g_sneg[h*BB+b];
        float mh = (sv >= 0.f) ? sv*sp : sv*sn;
        s_il2e[idx] = sv * LOG2E;
        s_mhat[idx] = mh * LOG2E;
    }
    for (int idx = tid; idx < 2048; idx += 256) {
        int h = idx >> 9, jl = idx & 511;
        sjs[idx] = g_s[(size_t)(h*BB+b)*NN + jc*JCHUNK + jl];
    }
    // adjacency -> bitmask, [word][row] (read once; all heads reuse)
    const int* adjb = adj + ((size_t)b*NN + it*128)*NN + jc*JCHUNK;
    for (int q = wid; q < 512; q += 8) {
        int ro = q >> 2, seg = q & 3;
        const int4 a4 = *(const int4*)(adjb + (size_t)ro*NN + seg*128 + lane*4);
        unsigned nib = (unsigned)(a4.x>0) | ((unsigned)(a4.y>0)<<1)
                     | ((unsigned)(a4.z>0)<<2) | ((unsigned)(a4.w>0)<<3);
        unsigned word = nib << ((lane & 7)*4);
        word |= __shfl_xor_sync(0xffffffffu, word, 1);
        word |= __shfl_xor_sync(0xffffffffu, word, 2);
        word |= __shfl_xor_sync(0xffffffffu, word, 4);
        if ((lane & 7) == 0) maskb[(seg*4 + (lane>>3))*128 + ro] = word;
    }
    // prologue: proj tile iter0 -> buffer 0 (padded BLD rows)
    {
        const int4* psrc = (const int4*)(g_proj + ((size_t)b*NN + jc*JCHUNK)*UU);
        for (int k = tid; k < 1024; k += 256) {
            int ro = k >> 3, cg = k & 7;
            *(int4*)(projB + ro*BLD + cg*8) = psrc[k];
        }
    }
    __syncthreads();

    int r_lo = wid*16 + g;          // this lane's two A rows
    int r_hi = r_lo + 8;

    // ldmatrix base offset within a B buffer (halves):
    // krow = (lane&7) + ((lane>>3)&1)*8 ; ncol-sub = (lane>>4)*8
    int ldm_row = (lane & 7) + ((lane >> 3) & 1)*8;
    uint32_t ldm_off = (uint32_t)(ldm_row*BLD + (lane >> 4)*8) * 2;

    float acc[8][4];                // D: cols q*8 + tg2 + i ; rows g / g+8
    float zac[4];                   // Z via ones-B mma

    for (int iter = 0; iter < 16; iter++) {
        int h = iter >> 2, jt = iter & 3;
        uint32_t bbase = projB_u32 + (uint32_t)(iter & 1)*(128*BLD*2) + ldm_off;

        if (iter) __syncthreads();   // prior-iter MMA reads of the other buffer done

        if (iter + 1 < 16) {         // prefetch next proj tile
            int hn = (iter+1) >> 2, jtn = (iter+1) & 3;
            const int4* psrc = (const int4*)(g_proj +
                ((size_t)(hn*BB+b)*NN + jc*JCHUNK + jtn*128)*UU);
            __half* pdst = projB + ((iter+1)&1)*(128*BLD);
            for (int k = tid; k < 1024; k += 256) {
                int ro = k >> 3, cg = k & 7;
                *(int4*)(pdst + ro*BLD + cg*8) = psrc[k];
            }
        }

        if (jt == 0) {
            #pragma unroll
            for (int q = 0; q < 8; q++)
                #pragma unroll
                for (int i = 0; i < 4; i++) acc[q][i] = 0.f;
            #pragma unroll
            for (int i = 0; i < 4; i++) zac[i] = 0.f;
        }

        float srl_lo = s_il2e[h*128 + r_lo], nmh_lo = -s_mhat[h*128 + r_lo];
        float srl_hi = s_il2e[h*128 + r_hi], nmh_hi = -s_mhat[h*128 + r_hi];
        unsigned mlo[4], mhi[4];
        #pragma unroll
        for (int w = 0; w < 4; w++) {
            mlo[w] = maskb[(jt*4 + w)*128 + r_lo];
            mhi[w] = maskb[(jt*4 + w)*128 + r_hi];
        }
        const float* sjp = sjs + h*512 + jt*128;

        #pragma unroll
        for (int ks = 0; ks < 8; ks++) {
            int c0 = ks*16 + tg2;
            float2 sj0 = *(const float2*)(sjp + c0);
            float2 sj1 = *(const float2*)(sjp + c0 + 8);
            unsigned wl = mlo[ks>>1], wh = mhi[ks>>1];
            int s0 = (ks & 1)*16 + tg2;

            uint32_t a0 = ex2pack(
                (wl >> s0)     & 1 ? fmaf(srl_lo, sj0.x, nmh_lo) : NEGBIG,
                (wl >> (s0+1)) & 1 ? fmaf(srl_lo, sj0.y, nmh_lo) : NEGBIG);
            uint32_t a1 = ex2pack(
                (wh >> s0)     & 1 ? fmaf(srl_hi, sj0.x, nmh_hi) : NEGBIG,
                (wh >> (s0+1)) & 1 ? fmaf(srl_hi, sj0.y, nmh_hi) : NEGBIG);
            uint32_t a2 = ex2pack(
                (wl >> (s0+8)) & 1 ? fmaf(srl_lo, sj1.x, nmh_lo) : NEGBIG,
                (wl >> (s0+9)) & 1 ? fmaf(srl_lo, sj1.y, nmh_lo) : NEGBIG);
            uint32_t a3 = ex2pack(
                (wh >> (s0+8)) & 1 ? fmaf(srl_hi, sj1.x, nmh_hi) : NEGBIG,
                (wh >> (s0+9)) & 1 ? fmaf(srl_hi, sj1.y, nmh_hi) : NEGBIG);

            uint32_t kroff = (uint32_t)(ks*16*BLD*2);
            #pragma unroll
            for (int nt = 0; nt < 4; nt++) {
                uint32_t r0, r1, r2, r3;
                LDSM_X4_TRANS(r0, r1, r2, r3, bbase + kroff + (uint32_t)(nt*16*2));
                MMA_F16(acc[2*nt],   a0, a1, a2, a3, r0, r1);
                MMA_F16(acc[2*nt+1], a0, a1, a2, a3, r2, r3);
            }
            MMA_F16(zac, a0, a1, a2, a3, ONEH2, ONEH2);
        }

        if (jt == 3) {
            float* ob = g_Opart + (((size_t)cidx*HH + h)*128 + wid*16)*64;
            #pragma unroll
            for (int q = 0; q < 8; q++) {
                *(float2*)(ob + (size_t)g*64      + q*8 + tg2) = make_float2(acc[q][0], acc[q][1]);
                *(float2*)(ob + (size_t)(g+8)*64  + q*8 + tg2) = make_float2(acc[q][2], acc[q][3]);
            }
            if ((lane & 3) == 0) {
                float* zb = g_Zpart + ((size_t)cidx*HH + h)*128;
                zb[r_lo] = zac[0];
                zb[r_hi] = zac[2];
            }
        }
    }
}

// ---------------- Kernel 3: combine, divide, head-mean (1 thread / element) -
__global__ __launch_bounds__(256) void k_final(float* __restrict__ out)
{
    int idx = blockIdx.x*256 + threadIdx.x;      // 0 .. 524287
    int u = idx & 63;
    int n = (idx >> 6) & 2047;
    int b = idx >> 17;
    int it = n >> 7, r = n & 127;

    float acc = 0.f;
    #pragma unroll
    for (int h = 0; h < HH; h++) {
        float z = 0.f, num = 0.f;
        #pragma unroll
        for (int jcc = 0; jcc < JC; jcc++) {
            int c = (b*16 + it)*4 + jcc;
            size_t base = ((size_t)c*HH + h)*128 + r;
            z   += g_Zpart[base];
            num += g_Opart[base*64 + u];
        }
        acc += num / z;
    }
    out[idx] = 0.25f * acc;
}

// ---------------- launch ----------------------------------------------------
extern "C" void kernel_launch(void* const* d_in, const int* in_sizes, int n_in,
                              void* d_out, int out_size)
{
    const float* x   = (const float*)d_in[0];
    const int*   adj = (const int*)d_in[1];
    const float* W   = (const float*)d_in[2];
    const float* bia = (const float*)d_in[3];
    const float* aw  = (const float*)d_in[4];
    const float* ab  = (const float*)d_in[5];
    float* out = (float*)d_out;
    (void)in_sizes; (void)n_in; (void)out_size;

    cudaFuncSetAttribute(k_attn, cudaFuncAttributeMaxDynamicSharedMemorySize, SMEM_ATTN);

    dim3 g1(NN/256, BB, HH);
    k_proj<<<g1, 256>>>(x, W, bia, aw, ab);
    k_minmax<<<HH*BB, 256>>>();
    k_attn<<<NCTA2, 256, SMEM_ATTN>>>(adj);
    k_final<<<(BB*NN*UU)/256, 256>>>(out);
}

// round 7
// speedup vs baseline: 2.7722x; 1.1595x over previous
#include <cuda_runtime.h>
#include <cuda_fp16.h>
#include <cstdint>

#define HH 4
#define BB 4
#define NN 2048
#define FF 128
#define UU 64
#define LOG2E 1.4426950408889634f

#define JC 4
#define JCHUNK 512
#define NCTA2 (BB*16*JC)   // 256
#define BLD 72             // proj B tile row stride in halves (144 B): conflict-free

// ---------------- scratch ----------------------------------------------------
__device__ __half g_proj[HH*BB*NN*UU];        // 4 MB  fp16 projections
__device__ float  g_s[HH*BB*NN];
__device__ float  g_spos[HH*BB];
__device__ float  g_sneg[HH*BB];
__device__ __half g_Opart[8388608];           // [NCTA2][H][128][64] fp16 partials (16.8 MB)
__device__ float  g_Zpart[NCTA2*HH*128];

__device__ __forceinline__ uint32_t smem_u32(const void* p) {
    uint32_t a;
    asm("{ .reg .u64 t; cvta.to.shared.u64 t, %1; cvt.u32.u64 %0, t; }" : "=r"(a) : "l"(p));
    return a;
}

// pack two fp32 args to half2 and take ex2 of both
__device__ __forceinline__ uint32_t ex2pack(float x, float y) {
    __half2 hh = __floats2half2_rn(x, y);
    uint32_t u = *reinterpret_cast<uint32_t*>(&hh);
    asm("ex2.approx.f16x2 %0, %0;" : "+r"(u));
    return u;
}
__device__ __forceinline__ uint32_t hmul2u(uint32_t e, uint32_t m) {
    __half2 a = *reinterpret_cast<__half2*>(&e);
    __half2 b = *reinterpret_cast<__half2*>(&m);
    __half2 c = __hmul2(a, b);
    return *reinterpret_cast<uint32_t*>(&c);
}

#define MMA_F16(d, a0,a1,a2,a3, b0,b1) \
    asm volatile("mma.sync.aligned.m16n8k16.row.col.f32.f16.f16.f32 " \
        "{%0,%1,%2,%3}, {%4,%5,%6,%7}, {%8,%9}, {%0,%1,%2,%3};" \
        : "+f"((d)[0]), "+f"((d)[1]), "+f"((d)[2]), "+f"((d)[3]) \
        : "r"(a0), "r"(a1), "r"(a2), "r"(a3), "r"(b0), "r"(b1))

#define LDSM_X4_TRANS(r0,r1,r2,r3, addr) \
    asm volatile("ldmatrix.sync.aligned.m8n8.x4.trans.shared.b16 {%0,%1,%2,%3}, [%4];" \
        : "=r"(r0), "=r"(r1), "=r"(r2), "=r"(r3) : "r"(addr))

// ---------------- Kernel 1: proj = relu(x@W + b), s = proj.a_w + a_b --------
__global__ __launch_bounds__(256) void k_proj(const float* __restrict__ x,
                                              const float* __restrict__ W,
                                              const float* __restrict__ bias,
                                              const float* __restrict__ a_w,
                                              const float* __restrict__ a_b)
{
    __shared__ float Wsm[16][UU];
    __shared__ float xsm[256][17];
    __shared__ float bsm[UU], awsm[UU];

    int h = blockIdx.z, b = blockIdx.y;
    int n0 = blockIdx.x * 256;
    int tid = threadIdx.x;

    if (tid < UU) { bsm[tid] = bias[h*UU + tid]; awsm[tid] = a_w[h*UU + tid]; }

    float acc[UU];
    #pragma unroll
    for (int u = 0; u < UU; u++) acc[u] = 0.f;

    const float* xb = x + ((size_t)b*NN + n0)*FF;
    const float* Wb = W + (size_t)h*FF*UU;

    for (int fc = 0; fc < FF; fc += 16) {
        __syncthreads();
        for (int k = tid; k < 16*UU; k += 256)
            Wsm[k>>6][k&63] = Wb[(size_t)(fc + (k>>6))*UU + (k&63)];
        for (int k = tid; k < 256*16; k += 256) {
            int r = k >> 4, f = k & 15;
            xsm[r][f] = xb[(size_t)r*FF + fc + f];
        }
        __syncthreads();
        #pragma unroll
        for (int f = 0; f < 16; f++) {
            float xv = xsm[tid][f];
            #pragma unroll
            for (int u = 0; u < UU; u += 4) {
                float4 wv = *(const float4*)&Wsm[f][u];
                acc[u]   = fmaf(xv, wv.x, acc[u]);
                acc[u+1] = fmaf(xv, wv.y, acc[u+1]);
                acc[u+2] = fmaf(xv, wv.z, acc[u+2]);
                acc[u+3] = fmaf(xv, wv.w, acc[u+3]);
            }
        }
    }

    float s = 0.f;
    __half2* pout = (__half2*)(g_proj + ((size_t)(h*BB+b)*NN + n0 + tid)*UU);
    #pragma unroll
    for (int u = 0; u < UU; u += 2) {
        float p0 = fmaxf(acc[u]   + bsm[u],   0.f);
        float p1 = fmaxf(acc[u+1] + bsm[u+1], 0.f);
        s = fmaf(p0, awsm[u],   s);
        s = fmaf(p1, awsm[u+1], s);
        pout[u>>1] = __floats2half2_rn(p0, p1);
    }
    s += a_b[h];
    g_s[(size_t)(h*BB+b)*NN + n0 + tid] = s;
}

// ---------------- Kernel 1b: per-(h,b) max/min of s --------------------------
__global__ __launch_bounds__(256) void k_minmax()
{
    __shared__ float smx[256], smn[256];
    int hb = blockIdx.x, tid = threadIdx.x;
    float mx = -1e30f, mn = 1e30f;
    for (int k = tid; k < NN; k += 256) {
        float v = g_s[(size_t)hb*NN + k];
        mx = fmaxf(mx, v); mn = fminf(mn, v);
    }
    smx[tid] = mx; smn[tid] = mn;
    __syncthreads();
    for (int off = 128; off > 0; off >>= 1) {
        if (tid < off) {
            smx[tid] = fmaxf(smx[tid], smx[tid+off]);
            smn[tid] = fminf(smn[tid], smn[tid+off]);
        }
        __syncthreads();
    }
    if (tid == 0) { g_spos[hb] = smx[0]; g_sneg[hb] = smn[0]; }
}

// ---------------- Kernel 2: register-A mma.m16n8k16 attention ---------------
// smem layout (bytes):
//   0      s_il2e[512]f        2048
//   2048   s_mhat[512]f        2048
//   4096   sjs[2048]f          8192
//   12288  maskb[16][128]u     8192
//   20480  lutm[4]u            16 (+16 pad)
//   20512  projB[2][128*BLD]h  36864
//   total  57376
#define SMEM_ATTN 57376
#define ONEH2 0x3C003C00u

__global__ __launch_bounds__(256,2) void k_attn(const int* __restrict__ adj)
{
    extern __shared__ char smem[];
    float*    s_il2e = (float*)(smem);
    float*    s_mhat = (float*)(smem + 2048);
    float*    sjs    = (float*)(smem + 4096);
    unsigned* maskb  = (unsigned*)(smem + 12288);
    unsigned* lutm   = (unsigned*)(smem + 20480);
    __half*   projB  = (__half*)(smem + 20512);
    uint32_t  projB_u32 = smem_u32(projB);

    int cidx = blockIdx.x;
    int b = cidx >> 6, it = (cidx >> 2) & 15, jc = cidx & 3;
    int tid = threadIdx.x, lane = tid & 31, wid = tid >> 5;
    int g = lane >> 2, tg2 = (lane & 3)*2;

    if (tid < 4)
        lutm[tid] = ((tid & 1) ? 0x00003C00u : 0u) | ((tid & 2) ? 0x3C000000u : 0u);

    // s_i scaled + safe row max bound (global over j)
    for (int idx = tid; idx < 512; idx += 256) {
        int h = idx >> 7, r = idx & 127;
        float sv = g_s[(size_t)(h*BB+b)*NN + it*128 + r];
        float sp = g_spos[h*BB+b], sn = g_sneg[h*BB+b];
        float mh = (sv >= 0.f) ? sv*sp : sv*sn;
        s_il2e[idx] = sv * LOG2E;
        s_mhat[idx] = mh * LOG2E;
    }
    for (int idx = tid; idx < 2048; idx += 256) {
        int h = idx >> 9, jl = idx & 511;
        sjs[idx] = g_s[(size_t)(h*BB+b)*NN + jc*JCHUNK + jl];
    }
    // adjacency -> bitmask, [word][row] (read once; all heads reuse)
    const int* adjb = adj + ((size_t)b*NN + it*128)*NN + jc*JCHUNK;
    for (int q = wid; q < 512; q += 8) {
        int ro = q >> 2, seg = q & 3;
        const int4 a4 = *(const int4*)(adjb + (size_t)ro*NN + seg*128 + lane*4);
        unsigned nib = (unsigned)(a4.x>0) | ((unsigned)(a4.y>0)<<1)
                     | ((unsigned)(a4.z>0)<<2) | ((unsigned)(a4.w>0)<<3);
        unsigned word = nib << ((lane & 7)*4);
        word |= __shfl_xor_sync(0xffffffffu, word, 1);
        word |= __shfl_xor_sync(0xffffffffu, word, 2);
        word |= __shfl_xor_sync(0xffffffffu, word, 4);
        if ((lane & 7) == 0) maskb[(seg*4 + (lane>>3))*128 + ro] = word;
    }
    // prologue: proj tile iter0 -> buffer 0 (padded BLD rows)
    {
        const int4* psrc = (const int4*)(g_proj + ((size_t)b*NN + jc*JCHUNK)*UU);
        for (int k = tid; k < 1024; k += 256) {
            int ro = k >> 3, cg = k & 7;
            *(int4*)(projB + ro*BLD + cg*8) = psrc[k];
        }
    }
    __syncthreads();

    int r_lo = wid*16 + g;          // this lane's two A rows
    int r_hi = r_lo + 8;

    // ldmatrix base offset within a B buffer (halves)
    int ldm_row = (lane & 7) + ((lane >> 3) & 1)*8;
    uint32_t ldm_off = (uint32_t)(ldm_row*BLD + (lane >> 4)*8) * 2;

    float acc[8][4];                // D: cols q*8 + tg2 + i ; rows g / g+8
    float zac[4];                   // Z via ones-B mma

    for (int iter = 0; iter < 16; iter++) {
        int h = iter >> 2, jt = iter & 3;
        uint32_t bbase = projB_u32 + (uint32_t)(iter & 1)*(128*BLD*2) + ldm_off;

        if (iter) __syncthreads();   // prior-iter MMA reads of the other buffer done

        if (iter + 1 < 16) {         // prefetch next proj tile
            int hn = (iter+1) >> 2, jtn = (iter+1) & 3;
            const int4* psrc = (const int4*)(g_proj +
                ((size_t)(hn*BB+b)*NN + jc*JCHUNK + jtn*128)*UU);
            __half* pdst = projB + ((iter+1)&1)*(128*BLD);
            for (int k = tid; k < 1024; k += 256) {
                int ro = k >> 3, cg = k & 7;
                *(int4*)(pdst + ro*BLD + cg*8) = psrc[k];
            }
        }

        if (jt == 0) {
            #pragma unroll
            for (int q = 0; q < 8; q++)
                #pragma unroll
                for (int i = 0; i < 4; i++) acc[q][i] = 0.f;
            #pragma unroll
            for (int i = 0; i < 4; i++) zac[i] = 0.f;
        }

        float srl_lo = s_il2e[h*128 + r_lo], nmh_lo = -s_mhat[h*128 + r_lo];
        float srl_hi = s_il2e[h*128 + r_hi], nmh_hi = -s_mhat[h*128 + r_hi];
        unsigned mlo[4], mhi[4];
        #pragma unroll
        for (int w = 0; w < 4; w++) {
            mlo[w] = maskb[(jt*4 + w)*128 + r_lo] >> tg2;
            mhi[w] = maskb[(jt*4 + w)*128 + r_hi] >> tg2;
        }
        const float* sjp = sjs + h*512 + jt*128;

        #pragma unroll
        for (int ks = 0; ks < 8; ks++) {
            int c0 = ks*16 + tg2;
            float2 sj0 = *(const float2*)(sjp + c0);
            float2 sj1 = *(const float2*)(sjp + c0 + 8);
            unsigned wl = mlo[ks>>1], wh = mhi[ks>>1];
            int sh = (ks & 1)*16;

            uint32_t a0 = hmul2u(
                ex2pack(fmaf(srl_lo, sj0.x, nmh_lo), fmaf(srl_lo, sj0.y, nmh_lo)),
                lutm[(wl >> sh) & 3]);
            uint32_t a1 = hmul2u(
                ex2pack(fmaf(srl_hi, sj0.x, nmh_hi), fmaf(srl_hi, sj0.y, nmh_hi)),
                lutm[(wh >> sh) & 3]);
            uint32_t a2 = hmul2u(
                ex2pack(fmaf(srl_lo, sj1.x, nmh_lo), fmaf(srl_lo, sj1.y, nmh_lo)),
                lutm[(wl >> (sh+8)) & 3]);
            uint32_t a3 = hmul2u(
                ex2pack(fmaf(srl_hi, sj1.x, nmh_hi), fmaf(srl_hi, sj1.y, nmh_hi)),
                lutm[(wh >> (sh+8)) & 3]);

            uint32_t kroff = (uint32_t)(ks*16*BLD*2);
            #pragma unroll
            for (int nt = 0; nt < 4; nt++) {
                uint32_t r0, r1, r2, r3;
                LDSM_X4_TRANS(r0, r1, r2, r3, bbase + kroff + (uint32_t)(nt*16*2));
                MMA_F16(acc[2*nt],   a0, a1, a2, a3, r0, r1);
                MMA_F16(acc[2*nt+1], a0, a1, a2, a3, r2, r3);
            }
            MMA_F16(zac, a0, a1, a2, a3, ONEH2, ONEH2);
        }

        if (jt == 3) {
            __half* ob = g_Opart + (((size_t)cidx*HH + h)*128 + wid*16)*64;
            #pragma unroll
            for (int q = 0; q < 8; q++) {
                *(__half2*)(ob + (size_t)g*64     + q*8 + tg2) = __floats2half2_rn(acc[q][0], acc[q][1]);
                *(__half2*)(ob + (size_t)(g+8)*64 + q*8 + tg2) = __floats2half2_rn(acc[q][2], acc[q][3]);
            }
            if ((lane & 3) == 0) {
                float* zb = g_Zpart + ((size_t)cidx*HH + h)*128;
                zb[r_lo] = zac[0];
                zb[r_hi] = zac[2];
            }
        }
    }
}

// ---------------- Kernel 3: combine, divide, head-mean (1 thread / element) -
__global__ __launch_bounds__(256) void k_final(float* __restrict__ out)
{
    int idx = blockIdx.x*256 + threadIdx.x;      // 0 .. 524287
    int u = idx & 63;
    int n = (idx >> 6) & 2047;
    int b = idx >> 17;
    int it = n >> 7, r = n & 127;

    float acc = 0.f;
    #pragma unroll
    for (int h = 0; h < HH; h++) {
        float z = 0.f, num = 0.f;
        #pragma unroll
        for (int jcc = 0; jcc < JC; jcc++) {
            int c = (b*16 + it)*4 + jcc;
            size_t base = ((size_t)c*HH + h)*128 + r;
            z   += g_Zpart[base];
            num += __half2float(g_Opart[base*64 + u]);
        }
        acc += num / z;
    }
    out[idx] = 0.25f * acc;
}

// ---------------- launch ----------------------------------------------------
extern "C" void kernel_launch(void* const* d_in, const int* in_sizes, int n_in,
                              void* d_out, int out_size)
{
    const float* x   = (const float*)d_in[0];
    const int*   adj = (const int*)d_in[1];
    const float* W   = (const float*)d_in[2];
    const float* bia = (const float*)d_in[3];
    const float* aw  = (const float*)d_in[4];
    const float* ab  = (const float*)d_in[5];
    float* out = (float*)d_out;
    (void)in_sizes; (void)n_in; (void)out_size;

    cudaFuncSetAttribute(k_attn, cudaFuncAttributeMaxDynamicSharedMemorySize, SMEM_ATTN);

    dim3 g1(NN/256, BB, HH);
    k_proj<<<g1, 256>>>(x, W, bia, aw, ab);
    k_minmax<<<HH*BB, 256>>>();
    k_attn<<<NCTA2, 256, SMEM_ATTN>>>(adj);
    k_final<<<(BB*NN*UU)/256, 256>>>(out);
}

// round 8
// speedup vs baseline: 2.9702x; 1.0714x over previous
#include <cuda_runtime.h>
#include <cuda_fp16.h>
#include <cstdint>

#define HH 4
#define BB 4
#define NN 2048
#define FF 128
#define UU 64
#define LOG2E 1.4426950408889634f

#define JC 4
#define JCHUNK 512
#define NCTA2 (BB*16*JC)   // 256
#define BLD 72             // proj B tile row stride in halves (144 B): conflict-free

// ---------------- scratch ----------------------------------------------------
__device__ __half g_proj[HH*BB*NN*UU];        // 4 MB  fp16 projections
__device__ float  g_s[HH*BB*NN];
__device__ float  g_spos[HH*BB];
__device__ float  g_sneg[HH*BB];
__device__ __half g_Opart[8388608];           // [NCTA2][H][128][64] fp16 partials
__device__ float  g_Zpart[NCTA2*HH*128];

__device__ __forceinline__ uint32_t smem_u32(const void* p) {
    uint32_t a;
    asm("{ .reg .u64 t; cvta.to.shared.u64 t, %1; cvt.u32.u64 %0, t; }" : "=r"(a) : "l"(p));
    return a;
}

__device__ __forceinline__ uint32_t ex2pack(float x, float y) {
    __half2 hh = __floats2half2_rn(x, y);
    uint32_t u = *reinterpret_cast<uint32_t*>(&hh);
    asm("ex2.approx.f16x2 %0, %0;" : "+r"(u));
    return u;
}
__device__ __forceinline__ uint32_t hmul2u(uint32_t e, uint32_t m) {
    __half2 a = *reinterpret_cast<__half2*>(&e);
    __half2 b = *reinterpret_cast<__half2*>(&m);
    __half2 c = __hmul2(a, b);
    return *reinterpret_cast<uint32_t*>(&c);
}

#define MMA_F16(d, a0,a1,a2,a3, b0,b1) \
    asm volatile("mma.sync.aligned.m16n8k16.row.col.f32.f16.f16.f32 " \
        "{%0,%1,%2,%3}, {%4,%5,%6,%7}, {%8,%9}, {%0,%1,%2,%3};" \
        : "+f"((d)[0]), "+f"((d)[1]), "+f"((d)[2]), "+f"((d)[3]) \
        : "r"(a0), "r"(a1), "r"(a2), "r"(a3), "r"(b0), "r"(b1))

#define LDSM_X4_TRANS(r0,r1,r2,r3, addr) \
    asm volatile("ldmatrix.sync.aligned.m8n8.x4.trans.shared.b16 {%0,%1,%2,%3}, [%4];" \
        : "=r"(r0), "=r"(r1), "=r"(r2), "=r"(r3) : "r"(addr))

#define CP_ASYNC_16(dst_u32, src) \
    asm volatile("cp.async.cg.shared.global [%0], [%1], 16;" \
        :: "r"(dst_u32), "l"(src) : "memory")
#define CP_ASYNC_COMMIT() asm volatile("cp.async.commit_group;" ::: "memory")
#define CP_ASYNC_WAIT0()  asm volatile("cp.async.wait_group 0;" ::: "memory")

// ---------------- Kernel 1: proj = relu(x@W + b), s = proj.a_w + a_b --------
__global__ __launch_bounds__(256) void k_proj(const float* __restrict__ x,
                                              const float* __restrict__ W,
                                              const float* __restrict__ bias,
                                              const float* __restrict__ a_w,
                                              const float* __restrict__ a_b)
{
    __shared__ float Wsm[16][UU];
    __shared__ float xsm[256][17];
    __shared__ float bsm[UU], awsm[UU];

    int h = blockIdx.z, b = blockIdx.y;
    int n0 = blockIdx.x * 256;
    int tid = threadIdx.x;

    if (tid < UU) { bsm[tid] = bias[h*UU + tid]; awsm[tid] = a_w[h*UU + tid]; }

    float acc[UU];
    #pragma unroll
    for (int u = 0; u < UU; u++) acc[u] = 0.f;

    const float* xb = x + ((size_t)b*NN + n0)*FF;
    const float* Wb = W + (size_t)h*FF*UU;

    for (int fc = 0; fc < FF; fc += 16) {
        __syncthreads();
        for (int k = tid; k < 16*UU; k += 256)
            Wsm[k>>6][k&63] = Wb[(size_t)(fc + (k>>6))*UU + (k&63)];
        for (int k = tid; k < 256*16; k += 256) {
            int r = k >> 4, f = k & 15;
            xsm[r][f] = xb[(size_t)r*FF + fc + f];
        }
        __syncthreads();
        #pragma unroll
        for (int f = 0; f < 16; f++) {
            float xv = xsm[tid][f];
            #pragma unroll
            for (int u = 0; u < UU; u += 4) {
                float4 wv = *(const float4*)&Wsm[f][u];
                acc[u]   = fmaf(xv, wv.x, acc[u]);
                acc[u+1] = fmaf(xv, wv.y, acc[u+1]);
                acc[u+2] = fmaf(xv, wv.z, acc[u+2]);
                acc[u+3] = fmaf(xv, wv.w, acc[u+3]);
            }
        }
    }

    float s = 0.f;
    __half2* pout = (__half2*)(g_proj + ((size_t)(h*BB+b)*NN + n0 + tid)*UU);
    #pragma unroll
    for (int u = 0; u < UU; u += 2) {
        float p0 = fmaxf(acc[u]   + bsm[u],   0.f);
        float p1 = fmaxf(acc[u+1] + bsm[u+1], 0.f);
        s = fmaf(p0, awsm[u],   s);
        s = fmaf(p1, awsm[u+1], s);
        pout[u>>1] = __floats2half2_rn(p0, p1);
    }
    s += a_b[h];
    g_s[(size_t)(h*BB+b)*NN + n0 + tid] = s;
}

// ---------------- Kernel 1b: per-(h,b) max/min of s --------------------------
__global__ __launch_bounds__(256) void k_minmax()
{
    __shared__ float smx[256], smn[256];
    int hb = blockIdx.x, tid = threadIdx.x;
    float mx = -1e30f, mn = 1e30f;
    for (int k = tid; k < NN; k += 256) {
        float v = g_s[(size_t)hb*NN + k];
        mx = fmaxf(mx, v); mn = fminf(mn, v);
    }
    smx[tid] = mx; smn[tid] = mn;
    __syncthreads();
    for (int off = 128; off > 0; off >>= 1) {
        if (tid < off) {
            smx[tid] = fmaxf(smx[tid], smx[tid+off]);
            smn[tid] = fminf(smn[tid], smn[tid+off]);
        }
        __syncthreads();
    }
    if (tid == 0) { g_spos[hb] = smx[0]; g_sneg[hb] = smn[0]; }
}

// ---------------- Kernel 2: register-A mma.m16n8k16 attention ---------------
// smem layout (bytes):
//   0      s_il2e[512]f        2048
//   2048   s_mhat[512]f        2048
//   4096   sjs[2048]f          8192
//   12288  maskb[16][128]u     8192
//   20480  lutm[4]u            16 (+16 pad)
//   20512  projB[2][128*BLD]h  36864
//   total  57376  (x3 CTAs = 172KB)
#define SMEM_ATTN 57376
#define ONEH2 0x3C003C00u

__global__ __launch_bounds__(256,3) void k_attn(const int* __restrict__ adj)
{
    extern __shared__ char smem[];
    float*    s_il2e = (float*)(smem);
    float*    s_mhat = (float*)(smem + 2048);
    float*    sjs    = (float*)(smem + 4096);
    unsigned* maskb  = (unsigned*)(smem + 12288);
    unsigned* lutm   = (unsigned*)(smem + 20480);
    __half*   projB  = (__half*)(smem + 20512);
    uint32_t  projB_u32 = smem_u32(projB);

    int cidx = blockIdx.x;
    int b = cidx >> 6, it = (cidx >> 2) & 15, jc = cidx & 3;
    int tid = threadIdx.x, lane = tid & 31, wid = tid >> 5;
    int g = lane >> 2, tg2 = (lane & 3)*2;

    if (tid < 4)
        lutm[tid] = ((tid & 1) ? 0x00003C00u : 0u) | ((tid & 2) ? 0x3C000000u : 0u);

    // s_i scaled + safe row max bound (global over j)
    for (int idx = tid; idx < 512; idx += 256) {
        int h = idx >> 7, r = idx & 127;
        float sv = g_s[(size_t)(h*BB+b)*NN + it*128 + r];
        float sp = g_spos[h*BB+b], sn = g_sneg[h*BB+b];
        float mh = (sv >= 0.f) ? sv*sp : sv*sn;
        s_il2e[idx] = sv * LOG2E;
        s_mhat[idx] = mh * LOG2E;
    }
    for (int idx = tid; idx < 2048; idx += 256) {
        int h = idx >> 9, jl = idx & 511;
        sjs[idx] = g_s[(size_t)(h*BB+b)*NN + jc*JCHUNK + jl];
    }
    // adjacency -> bitmask, [word][row] (read once; all heads reuse)
    const int* adjb = adj + ((size_t)b*NN + it*128)*NN + jc*JCHUNK;
    for (int q = wid; q < 512; q += 8) {
        int ro = q >> 2, seg = q & 3;
        const int4 a4 = *(const int4*)(adjb + (size_t)ro*NN + seg*128 + lane*4);
        unsigned nib = (unsigned)(a4.x>0) | ((unsigned)(a4.y>0)<<1)
                     | ((unsigned)(a4.z>0)<<2) | ((unsigned)(a4.w>0)<<3);
        unsigned word = nib << ((lane & 7)*4);
        word |= __shfl_xor_sync(0xffffffffu, word, 1);
        word |= __shfl_xor_sync(0xffffffffu, word, 2);
        word |= __shfl_xor_sync(0xffffffffu, word, 4);
        if ((lane & 7) == 0) maskb[(seg*4 + (lane>>3))*128 + ro] = word;
    }
    // prologue: proj tile iter0 -> buffer 0 via cp.async
    {
        const char* psrc = (const char*)(g_proj + ((size_t)b*NN + jc*JCHUNK)*UU);
        #pragma unroll
        for (int c = 0; c < 4; c++) {
            int k = tid + c*256;               // 0..1023
            int ro = k >> 3, cg = k & 7;
            CP_ASYNC_16(projB_u32 + (uint32_t)(ro*BLD + cg*8)*2, psrc + (size_t)k*16);
        }
        CP_ASYNC_COMMIT();
    }
    CP_ASYNC_WAIT0();
    __syncthreads();

    int r_lo = wid*16 + g;
    int r_hi = r_lo + 8;

    int ldm_row = (lane & 7) + ((lane >> 3) & 1)*8;
    uint32_t ldm_off = (uint32_t)(ldm_row*BLD + (lane >> 4)*8) * 2;

    float acc[8][4];
    float zac[4];

    for (int iter = 0; iter < 16; iter++) {
        int h = iter >> 2, jt = iter & 3;
        uint32_t bbase = projB_u32 + (uint32_t)(iter & 1)*(128*BLD*2) + ldm_off;

        if (iter) { CP_ASYNC_WAIT0(); __syncthreads(); }

        if (iter + 1 < 16) {   // background prefetch of next proj tile
            int hn = (iter+1) >> 2, jtn = (iter+1) & 3;
            const char* psrc = (const char*)(g_proj +
                ((size_t)(hn*BB+b)*NN + jc*JCHUNK + jtn*128)*UU);
            uint32_t pdst = projB_u32 + (uint32_t)((iter+1)&1)*(128*BLD*2);
            #pragma unroll
            for (int c = 0; c < 4; c++) {
                int k = tid + c*256;
                int ro = k >> 3, cg = k & 7;
                CP_ASYNC_16(pdst + (uint32_t)(ro*BLD + cg*8)*2, psrc + (size_t)k*16);
            }
            CP_ASYNC_COMMIT();
        }

        if (jt == 0) {
            #pragma unroll
            for (int q = 0; q < 8; q++)
                #pragma unroll
                for (int i = 0; i < 4; i++) acc[q][i] = 0.f;
            #pragma unroll
            for (int i = 0; i < 4; i++) zac[i] = 0.f;
        }

        float srl_lo = s_il2e[h*128 + r_lo], nmh_lo = -s_mhat[h*128 + r_lo];
        float srl_hi = s_il2e[h*128 + r_hi], nmh_hi = -s_mhat[h*128 + r_hi];
        const float* sjp = sjs + h*512 + jt*128;

        #pragma unroll
        for (int ks = 0; ks < 8; ks++) {
            int c0 = ks*16 + tg2;
            float2 sj0 = *(const float2*)(sjp + c0);
            float2 sj1 = *(const float2*)(sjp + c0 + 8);
            unsigned wl = maskb[(jt*4 + (ks>>1))*128 + r_lo] >> tg2;
            unsigned wh = maskb[(jt*4 + (ks>>1))*128 + r_hi] >> tg2;
            int sh = (ks & 1)*16;

            uint32_t a0 = hmul2u(
                ex2pack(fmaf(srl_lo, sj0.x, nmh_lo), fmaf(srl_lo, sj0.y, nmh_lo)),
                lutm[(wl >> sh) & 3]);
            uint32_t a1 = hmul2u(
                ex2pack(fmaf(srl_hi, sj0.x, nmh_hi), fmaf(srl_hi, sj0.y, nmh_hi)),
                lutm[(wh >> sh) & 3]);
            uint32_t a2 = hmul2u(
                ex2pack(fmaf(srl_lo, sj1.x, nmh_lo), fmaf(srl_lo, sj1.y, nmh_lo)),
                lutm[(wl >> (sh+8)) & 3]);
            uint32_t a3 = hmul2u(
                ex2pack(fmaf(srl_hi, sj1.x, nmh_hi), fmaf(srl_hi, sj1.y, nmh_hi)),
                lutm[(wh >> (sh+8)) & 3]);

            uint32_t kroff = (uint32_t)(ks*16*BLD*2);
            #pragma unroll
            for (int nt = 0; nt < 4; nt++) {
                uint32_t r0, r1, r2, r3;
                LDSM_X4_TRANS(r0, r1, r2, r3, bbase + kroff + (uint32_t)(nt*16*2));
                MMA_F16(acc[2*nt],   a0, a1, a2, a3, r0, r1);
                MMA_F16(acc[2*nt+1], a0, a1, a2, a3, r2, r3);
            }
            MMA_F16(zac, a0, a1, a2, a3, ONEH2, ONEH2);
        }

        if (jt == 3) {
            __half* ob = g_Opart + (((size_t)cidx*HH + h)*128 + wid*16)*64;
            #pragma unroll
            for (int q = 0; q < 8; q++) {
                *(__half2*)(ob + (size_t)g*64     + q*8 + tg2) = __floats2half2_rn(acc[q][0], acc[q][1]);
                *(__half2*)(ob + (size_t)(g+8)*64 + q*8 + tg2) = __floats2half2_rn(acc[q][2], acc[q][3]);
            }
            if ((lane & 3) == 0) {
                float* zb = g_Zpart + ((size_t)cidx*HH + h)*128;
                zb[r_lo] = zac[0];
                zb[r_hi] = zac[2];
            }
        }
    }
}

// ---------------- Kernel 3: combine, divide, head-mean (1 thread / u-pair) --
__global__ __launch_bounds__(256) void k_final(float* __restrict__ out)
{
    int idx = blockIdx.x*256 + threadIdx.x;      // 0 .. 262143
    int u2 = idx & 31;                           // u pair
    int n  = (idx >> 5) & 2047;
    int b  = idx >> 16;
    int it = n >> 7, r = n & 127;

    float ax = 0.f, ay = 0.f;
    #pragma unroll
    for (int h = 0; h < HH; h++) {
        float z = 0.f, nx = 0.f, ny = 0.f;
        #pragma unroll
        for (int jcc = 0; jcc < JC; jcc++) {
            int c = (b*16 + it)*4 + jcc;
            size_t base = ((size_t)c*HH + h)*128 + r;
            z += g_Zpart[base];
            __half2 v = *(const __half2*)(g_Opart + base*64 + u2*2);
            float2 f = __half22float2(v);
            nx += f.x; ny += f.y;
        }
        float rz = __frcp_rn(z);
        ax = fmaf(nx, rz, ax);
        ay = fmaf(ny, rz, ay);
    }
    *(float2*)(out + ((size_t)b*NN + n)*64 + u2*2) = make_float2(0.25f*ax, 0.25f*ay);
}

// ---------------- launch ----------------------------------------------------
extern "C" void kernel_launch(void* const* d_in, const int* in_sizes, int n_in,
                              void* d_out, int out_size)
{
    const float* x   = (const float*)d_in[0];
    const int*   adj = (const int*)d_in[1];
    const float* W   = (const float*)d_in[2];
    const float* bia = (const float*)d_in[3];
    const float* aw  = (const float*)d_in[4];
    const float* ab  = (const float*)d_in[5];
    float* out = (float*)d_out;
    (void)in_sizes; (void)n_in; (void)out_size;

    cudaFuncSetAttribute(k_attn, cudaFuncAttributeMaxDynamicSharedMemorySize, SMEM_ATTN);

    dim3 g1(NN/256, BB, HH);
    k_proj<<<g1, 256>>>(x, W, bia, aw, ab);
    k_minmax<<<HH*BB, 256>>>();
    k_attn<<<NCTA2, 256, SMEM_ATTN>>>(adj);
    k_final<<<(BB*NN*UU/2)/256, 256>>>(out);
}

// round 9
// speedup vs baseline: 3.1663x; 1.0660x over previous
#include <cuda_runtime.h>
#include <cuda_fp16.h>
#include <cstdint>

#define HH 4
#define BB 4
#define NN 2048
#define FF 128
#define UU 64
#define LOG2E 1.4426950408889634f

#define JC 4
#define JCHUNK 512
#define NCTA2 (BB*16*JC)   // 256
#define BLD 72             // proj B tile row stride in halves (144 B): conflict-free

// ---------------- scratch ----------------------------------------------------
__device__ __half g_proj[HH*BB*NN*UU];        // 4 MB  fp16 projections
__device__ float  g_s[HH*BB*NN];
__device__ float  g_spos[HH*BB];
__device__ float  g_sneg[HH*BB];
__device__ __half g_Opart[8388608];           // [NCTA2][H][128][64] fp16 partials
__device__ float  g_Zpart[NCTA2*HH*128];

__device__ __forceinline__ uint32_t smem_u32(const void* p) {
    uint32_t a;
    asm("{ .reg .u64 t; cvta.to.shared.u64 t, %1; cvt.u32.u64 %0, t; }" : "=r"(a) : "l"(p));
    return a;
}

__device__ __forceinline__ uint32_t ex2pack(float x, float y) {
    __half2 hh = __floats2half2_rn(x, y);
    uint32_t u = *reinterpret_cast<uint32_t*>(&hh);
    asm("ex2.approx.f16x2 %0, %0;" : "+r"(u));
    return u;
}
__device__ __forceinline__ uint32_t hmul2u(uint32_t e, uint32_t m) {
    __half2 a = *reinterpret_cast<__half2*>(&e);
    __half2 b = *reinterpret_cast<__half2*>(&m);
    __half2 c = __hmul2(a, b);
    return *reinterpret_cast<uint32_t*>(&c);
}

#define MMA_F16(d, a0,a1,a2,a3, b0,b1) \
    asm volatile("mma.sync.aligned.m16n8k16.row.col.f32.f16.f16.f32 " \
        "{%0,%1,%2,%3}, {%4,%5,%6,%7}, {%8,%9}, {%0,%1,%2,%3};" \
        : "+f"((d)[0]), "+f"((d)[1]), "+f"((d)[2]), "+f"((d)[3]) \
        : "r"(a0), "r"(a1), "r"(a2), "r"(a3), "r"(b0), "r"(b1))

#define LDSM_X4_TRANS(r0,r1,r2,r3, addr) \
    asm volatile("ldmatrix.sync.aligned.m8n8.x4.trans.shared.b16 {%0,%1,%2,%3}, [%4];" \
        : "=r"(r0), "=r"(r1), "=r"(r2), "=r"(r3) : "r"(addr))

#define CP_ASYNC_16(dst_u32, src) \
    asm volatile("cp.async.cg.shared.global [%0], [%1], 16;" \
        :: "r"(dst_u32), "l"(src) : "memory")
#define CP_ASYNC_COMMIT() asm volatile("cp.async.commit_group;" ::: "memory")
#define CP_ASYNC_WAIT0()  asm volatile("cp.async.wait_group 0;" ::: "memory")

// ---------------- Kernel 1: proj = relu(x@W + b), s = proj.a_w + a_b --------
// 128 threads, 128 rows per CTA, FFMA2 (f32x2) accumulation
__global__ __launch_bounds__(128) void k_proj(const float* __restrict__ x,
                                              const float* __restrict__ W,
                                              const float* __restrict__ bias,
                                              const float* __restrict__ a_w,
                                              const float* __restrict__ a_b)
{
    __shared__ __align__(16) float Wsm[16][UU];
    __shared__ float xsm[128][17];
    __shared__ float bsm[UU], awsm[UU];

    int h = blockIdx.z, b = blockIdx.y;
    int n0 = blockIdx.x * 128;
    int tid = threadIdx.x;

    if (tid < UU) { bsm[tid] = bias[h*UU + tid]; awsm[tid] = a_w[h*UU + tid]; }

    unsigned long long acc2[32];     // 32 packed f32x2 accumulators = 64 floats
    #pragma unroll
    for (int p = 0; p < 32; p++) acc2[p] = 0ULL;

    const float* xb = x + ((size_t)b*NN + n0)*FF;
    const float* Wb = W + (size_t)h*FF*UU;

    for (int fc = 0; fc < FF; fc += 16) {
        __syncthreads();
        for (int k = tid; k < 16*UU; k += 128)
            Wsm[k>>6][k&63] = Wb[(size_t)(fc + (k>>6))*UU + (k&63)];
        for (int k = tid; k < 128*16; k += 128) {
            int r = k >> 4, f = k & 15;
            xsm[r][f] = xb[(size_t)r*FF + fc + f];
        }
        __syncthreads();
        #pragma unroll
        for (int f = 0; f < 16; f++) {
            float xv = xsm[tid][f];
            unsigned long long xv2;
            asm("mov.b64 %0, {%1, %1};" : "=l"(xv2) : "f"(xv));
            #pragma unroll
            for (int p = 0; p < 32; p += 2) {
                ulonglong2 w2 = *(const ulonglong2*)&Wsm[f][p*2];
                asm("fma.rn.f32x2 %0, %1, %2, %0;" : "+l"(acc2[p])   : "l"(xv2), "l"(w2.x));
                asm("fma.rn.f32x2 %0, %1, %2, %0;" : "+l"(acc2[p+1]) : "l"(xv2), "l"(w2.y));
            }
        }
    }

    float s = 0.f;
    __half2* pout = (__half2*)(g_proj + ((size_t)(h*BB+b)*NN + n0 + tid)*UU);
    #pragma unroll
    for (int p = 0; p < 32; p++) {
        float a0, a1;
        asm("mov.b64 {%0,%1}, %2;" : "=f"(a0), "=f"(a1) : "l"(acc2[p]));
        float p0 = fmaxf(a0 + bsm[2*p],   0.f);
        float p1 = fmaxf(a1 + bsm[2*p+1], 0.f);
        s = fmaf(p0, awsm[2*p],   s);
        s = fmaf(p1, awsm[2*p+1], s);
        pout[p] = __floats2half2_rn(p0, p1);
    }
    s += a_b[h];
    g_s[(size_t)(h*BB+b)*NN + n0 + tid] = s;
}

// ---------------- Kernel 1b: per-(h,b) max/min of s --------------------------
__global__ __launch_bounds__(256) void k_minmax()
{
    __shared__ float smx[256], smn[256];
    int hb = blockIdx.x, tid = threadIdx.x;
    float mx = -1e30f, mn = 1e30f;
    for (int k = tid; k < NN; k += 256) {
        float v = g_s[(size_t)hb*NN + k];
        mx = fmaxf(mx, v); mn = fminf(mn, v);
    }
    smx[tid] = mx; smn[tid] = mn;
    __syncthreads();
    for (int off = 128; off > 0; off >>= 1) {
        if (tid < off) {
            smx[tid] = fmaxf(smx[tid], smx[tid+off]);
            smn[tid] = fminf(smn[tid], smn[tid+off]);
        }
        __syncthreads();
    }
    if (tid == 0) { g_spos[hb] = smx[0]; g_sneg[hb] = smn[0]; }
}

// ---------------- Kernel 2: register-A mma.m16n8k16 attention ---------------
// smem layout (bytes):
//   0      s_il2e[512]f        2048
//   2048   s_mhat[512]f        2048
//   4096   sjs[2048]f          8192
//   12288  maskb[16][128]u     8192
//   20480  lutm[4]u            16 (+16 pad)
//   20512  projB[2][128*BLD]h  36864
//   total  57376  (x3 CTAs = 172KB)
#define SMEM_ATTN 57376
#define ONEH2 0x3C003C00u

__global__ __launch_bounds__(256,3) void k_attn(const int* __restrict__ adj)
{
    extern __shared__ char smem[];
    float*    s_il2e = (float*)(smem);
    float*    s_mhat = (float*)(smem + 2048);
    float*    sjs    = (float*)(smem + 4096);
    unsigned* maskb  = (unsigned*)(smem + 12288);
    unsigned* lutm   = (unsigned*)(smem + 20480);
    __half*   projB  = (__half*)(smem + 20512);
    uint32_t  projB_u32 = smem_u32(projB);

    int cidx = blockIdx.x;
    int b = cidx >> 6, it = (cidx >> 2) & 15, jc = cidx & 3;
    int tid = threadIdx.x, lane = tid & 31, wid = tid >> 5;
    int g = lane >> 2, tg2 = (lane & 3)*2;

    if (tid < 4)
        lutm[tid] = ((tid & 1) ? 0x00003C00u : 0u) | ((tid & 2) ? 0x3C000000u : 0u);

    const int* adjbase = adj + ((size_t)b*NN + it*128)*NN + jc*JCHUNK;

    // mask builder for one 128-col segment (in-loop pipelined)
    auto build_mask = [&](int seg) {
        const int* ap = adjbase + seg*128;
        #pragma unroll
        for (int k = 0; k < 16; k++) {
            int ro = wid + k*8;
            const int4 a4 = *(const int4*)(ap + (size_t)ro*NN + lane*4);
            unsigned nib = (unsigned)(a4.x>0) | ((unsigned)(a4.y>0)<<1)
                         | ((unsigned)(a4.z>0)<<2) | ((unsigned)(a4.w>0)<<3);
            unsigned word = nib << ((lane & 7)*4);
            word |= __shfl_xor_sync(0xffffffffu, word, 1);
            word |= __shfl_xor_sync(0xffffffffu, word, 2);
            word |= __shfl_xor_sync(0xffffffffu, word, 4);
            if ((lane & 7) == 0) maskb[(seg*4 + (lane>>3))*128 + ro] = word;
        }
    };

    // s_i scaled + safe row max bound (global over j)
    for (int idx = tid; idx < 512; idx += 256) {
        int h = idx >> 7, r = idx & 127;
        float sv = g_s[(size_t)(h*BB+b)*NN + it*128 + r];
        float sp = g_spos[h*BB+b], sn = g_sneg[h*BB+b];
        float mh = (sv >= 0.f) ? sv*sp : sv*sn;
        s_il2e[idx] = sv * LOG2E;
        s_mhat[idx] = mh * LOG2E;
    }
    for (int idx = tid; idx < 2048; idx += 256) {
        int h = idx >> 9, jl = idx & 511;
        sjs[idx] = g_s[(size_t)(h*BB+b)*NN + jc*JCHUNK + jl];
    }
    // prologue: masks for seg 0 only; rest pipelined into the loop
    build_mask(0);
    // prologue: proj tile iter0 -> buffer 0 via cp.async
    {
        const char* psrc = (const char*)(g_proj + ((size_t)b*NN + jc*JCHUNK)*UU);
        #pragma unroll
        for (int c = 0; c < 4; c++) {
            int k = tid + c*256;
            int ro = k >> 3, cg = k & 7;
            CP_ASYNC_16(projB_u32 + (uint32_t)(ro*BLD + cg*8)*2, psrc + (size_t)k*16);
        }
        CP_ASYNC_COMMIT();
    }
    CP_ASYNC_WAIT0();
    __syncthreads();

    int r_lo = wid*16 + g;
    int r_hi = r_lo + 8;

    int ldm_row = (lane & 7) + ((lane >> 3) & 1)*8;
    uint32_t ldm_off = (uint32_t)(ldm_row*BLD + (lane >> 4)*8) * 2;

    float acc[8][4];
    float zac[4];

    for (int iter = 0; iter < 16; iter++) {
        int h = iter >> 2, jt = iter & 3;
        uint32_t bbase = projB_u32 + (uint32_t)(iter & 1)*(128*BLD*2) + ldm_off;

        if (iter) { CP_ASYNC_WAIT0(); __syncthreads(); }

        if (iter + 1 < 16) {   // background prefetch of next proj tile
            int hn = (iter+1) >> 2, jtn = (iter+1) & 3;
            const char* psrc = (const char*)(g_proj +
                ((size_t)(hn*BB+b)*NN + jc*JCHUNK + jtn*128)*UU);
            uint32_t pdst = projB_u32 + (uint32_t)((iter+1)&1)*(128*BLD*2);
            #pragma unroll
            for (int c = 0; c < 4; c++) {
                int k = tid + c*256;
                int ro = k >> 3, cg = k & 7;
                CP_ASYNC_16(pdst + (uint32_t)(ro*BLD + cg*8)*2, psrc + (size_t)k*16);
            }
            CP_ASYNC_COMMIT();
        }

        // pipelined mask build: seg jt+1 built during iter jt (h==0 only);
        // consumed at iter jt+1 after its __syncthreads
        if (h == 0 && jt < 3) build_mask(jt + 1);

        if (jt == 0) {
            #pragma unroll
            for (int q = 0; q < 8; q++)
                #pragma unroll
                for (int i = 0; i < 4; i++) acc[q][i] = 0.f;
            #pragma unroll
            for (int i = 0; i < 4; i++) zac[i] = 0.f;
        }

        float srl_lo = s_il2e[h*128 + r_lo], nmh_lo = -s_mhat[h*128 + r_lo];
        float srl_hi = s_il2e[h*128 + r_hi], nmh_hi = -s_mhat[h*128 + r_hi];
        const float* sjp = sjs + h*512 + jt*128;

        #pragma unroll
        for (int ks = 0; ks < 8; ks++) {
            int c0 = ks*16 + tg2;
            float2 sj0 = *(const float2*)(sjp + c0);
            float2 sj1 = *(const float2*)(sjp + c0 + 8);
            unsigned wl = maskb[(jt*4 + (ks>>1))*128 + r_lo] >> tg2;
            unsigned wh = maskb[(jt*4 + (ks>>1))*128 + r_hi] >> tg2;
            int sh = (ks & 1)*16;

            uint32_t a0 = hmul2u(
                ex2pack(fmaf(srl_lo, sj0.x, nmh_lo), fmaf(srl_lo, sj0.y, nmh_lo)),
                lutm[(wl >> sh) & 3]);
            uint32_t a1 = hmul2u(
                ex2pack(fmaf(srl_hi, sj0.x, nmh_hi), fmaf(srl_hi, sj0.y, nmh_hi)),
                lutm[(wh >> sh) & 3]);
            uint32_t a2 = hmul2u(
                ex2pack(fmaf(srl_lo, sj1.x, nmh_lo), fmaf(srl_lo, sj1.y, nmh_lo)),
                lutm[(wl >> (sh+8)) & 3]);
            uint32_t a3 = hmul2u(
                ex2pack(fmaf(srl_hi, sj1.x, nmh_hi), fmaf(srl_hi, sj1.y, nmh_hi)),
                lutm[(wh >> (sh+8)) & 3]);

            uint32_t kroff = (uint32_t)(ks*16*BLD*2);
            #pragma unroll
            for (int nt = 0; nt < 4; nt++) {
                uint32_t r0, r1, r2, r3;
                LDSM_X4_TRANS(r0, r1, r2, r3, bbase + kroff + (uint32_t)(nt*16*2));
                MMA_F16(acc[2*nt],   a0, a1, a2, a3, r0, r1);
                MMA_F16(acc[2*nt+1], a0, a1, a2, a3, r2, r3);
            }
            MMA_F16(zac, a0, a1, a2, a3, ONEH2, ONEH2);
        }

        if (jt == 3) {
            __half* ob = g_Opart + (((size_t)cidx*HH + h)*128 + wid*16)*64;
            #pragma unroll
            for (int q = 0; q < 8; q++) {
                *(__half2*)(ob + (size_t)g*64     + q*8 + tg2) = __floats2half2_rn(acc[q][0], acc[q][1]);
                *(__half2*)(ob + (size_t)(g+8)*64 + q*8 + tg2) = __floats2half2_rn(acc[q][2], acc[q][3]);
            }
            if ((lane & 3) == 0) {
                float* zb = g_Zpart + ((size_t)cidx*HH + h)*128;
                zb[r_lo] = zac[0];
                zb[r_hi] = zac[2];
            }
        }
    }
}

// ---------------- Kernel 3: combine, divide, head-mean (1 thread / u-pair) --
__global__ __launch_bounds__(256) void k_final(float* __restrict__ out)
{
    int idx = blockIdx.x*256 + threadIdx.x;      // 0 .. 262143
    int u2 = idx & 31;
    int n  = (idx >> 5) & 2047;
    int b  = idx >> 16;
    int it = n >> 7, r = n & 127;

    float ax = 0.f, ay = 0.f;
    #pragma unroll
    for (int h = 0; h < HH; h++) {
        float z = 0.f, nx = 0.f, ny = 0.f;
        #pragma unroll
        for (int jcc = 0; jcc < JC; jcc++) {
            int c = (b*16 + it)*4 + jcc;
            size_t base = ((size_t)c*HH + h)*128 + r;
            z += g_Zpart[base];
            __half2 v = *(const __half2*)(g_Opart + base*64 + u2*2);
            float2 f = __half22float2(v);
            nx += f.x; ny += f.y;
        }
        float rz = __frcp_rn(z);
        ax = fmaf(nx, rz, ax);
        ay = fmaf(ny, rz, ay);
    }
    *(float2*)(out + ((size_t)b*NN + n)*64 + u2*2) = make_float2(0.25f*ax, 0.25f*ay);
}

// ---------------- launch ----------------------------------------------------
extern "C" void kernel_launch(void* const* d_in, const int* in_sizes, int n_in,
                              void* d_out, int out_size)
{
    const float* x   = (const float*)d_in[0];
    const int*   adj = (const int*)d_in[1];
    const float* W   = (const float*)d_in[2];
    const float* bia = (const float*)d_in[3];
    const float* aw  = (const float*)d_in[4];
    const float* ab  = (const float*)d_in[5];
    float* out = (float*)d_out;
    (void)in_sizes; (void)n_in; (void)out_size;

    cudaFuncSetAttribute(k_attn, cudaFuncAttributeMaxDynamicSharedMemorySize, SMEM_ATTN);

    dim3 g1(NN/128, BB, HH);
    k_proj<<<g1, 128>>>(x, W, bia, aw, ab);
    k_minmax<<<HH*BB, 256>>>();
    k_attn<<<NCTA2, 256, SMEM_ATTN>>>(adj);
    k_final<<<(BB*NN*UU/2)/256, 256>>>(out);
}